// round 1
// baseline (speedup 1.0000x reference)
#include <cuda_runtime.h>

#define LSEQ 2048
#define DM   1024
#define DI   2048
#define DS   16

// ---------------- scratch (device globals: allocation-free) ----------------
__device__ float g_u[LSEQ * DM];        // rmsnorm output          8 MB
__device__ float g_xres[LSEQ * 2 * DI]; // in_proj out (x | res)  32 MB
__device__ float g_xconv[LSEQ * DI];    // conv+silu out          16 MB
__device__ float g_xdbl[LSEQ * 96];     // x_proj out (dr|B|C)
__device__ float g_delta[LSEQ * DI];    // softplus(dt_proj)      16 MB
__device__ float g_y[LSEQ * DI];        // scan out               16 MB

__device__ __forceinline__ float softplus_f(float x) {
    return fmaxf(x, 0.f) + log1pf(__expf(-fabsf(x)));
}

// ---------------- RMSNorm ----------------
__global__ void rmsnorm_kernel(const float* __restrict__ in,
                               const float* __restrict__ scale) {
    int l = blockIdx.x;
    int t = threadIdx.x;
    const float* row = in + (size_t)l * DM;
    float s = 0.f;
    #pragma unroll
    for (int i = t; i < DM; i += 256) { float v = row[i]; s += v * v; }
    __shared__ float red[256];
    red[t] = s; __syncthreads();
    for (int o = 128; o > 0; o >>= 1) {
        if (t < o) red[t] += red[t + o];
        __syncthreads();
    }
    float inv = rsqrtf(red[0] * (1.f / DM) + 1e-6f);
    for (int i = t; i < DM; i += 256)
        g_u[(size_t)l * DM + i] = row[i] * inv * scale[i];
}

// ---------------- generic 128x128x8 SGEMM, C = A*B (+epilogue) ----------------
// epi=0: plain store. epi=1: C = acc + extra[r*ldc + c] (elementwise add).
// epi=2: C = softplus(acc + extra[c]) (bias per column).
__global__ void __launch_bounds__(256) sgemm128(
    const float* __restrict__ A, int lda,
    const float* __restrict__ B, int ldb,
    float* __restrict__ C, int ldc,
    const float* __restrict__ extra,
    int K, int epi)
{
    __shared__ float As[2][8][128];
    __shared__ float Bs[2][8][128];
    int tid  = threadIdx.x;
    int bx   = blockIdx.x * 128;   // N offset
    int by   = blockIdx.y * 128;   // M offset
    int aRow = tid >> 1;
    int aCol = (tid & 1) << 2;
    int bRow = tid >> 5;
    int bCol = (tid & 31) << 2;
    const float* Aptr = A + (size_t)(by + aRow) * lda + aCol;
    const float* Bptr = B + (size_t)bRow * ldb + bx + bCol;
    int tx = tid & 15, ty = tid >> 4;

    float acc[8][8];
    #pragma unroll
    for (int i = 0; i < 8; ++i)
        #pragma unroll
        for (int j = 0; j < 8; ++j) acc[i][j] = 0.f;

    // prologue: tile 0 -> buffer 0
    {
        float4 a0 = *(const float4*)Aptr;
        float4 b0 = *(const float4*)Bptr;
        As[0][aCol + 0][aRow] = a0.x;
        As[0][aCol + 1][aRow] = a0.y;
        As[0][aCol + 2][aRow] = a0.z;
        As[0][aCol + 3][aRow] = a0.w;
        *(float4*)&Bs[0][bRow][bCol] = b0;
    }
    __syncthreads();

    int ntiles = K >> 3;
    for (int tk = 0; tk < ntiles; ++tk) {
        int cur = tk & 1;
        float4 an, bn;
        bool more = (tk + 1 < ntiles);
        if (more) {
            an = *(const float4*)(Aptr + (size_t)(tk + 1) * 8);
            bn = *(const float4*)(Bptr + (size_t)(tk + 1) * 8 * ldb);
        }
        #pragma unroll
        for (int kk = 0; kk < 8; ++kk) {
            float4 ar0 = *(const float4*)&As[cur][kk][ty * 4];
            float4 ar1 = *(const float4*)&As[cur][kk][64 + ty * 4];
            float4 br0 = *(const float4*)&Bs[cur][kk][tx * 4];
            float4 br1 = *(const float4*)&Bs[cur][kk][64 + tx * 4];
            float av[8] = {ar0.x, ar0.y, ar0.z, ar0.w, ar1.x, ar1.y, ar1.z, ar1.w};
            float bv[8] = {br0.x, br0.y, br0.z, br0.w, br1.x, br1.y, br1.z, br1.w};
            #pragma unroll
            for (int i = 0; i < 8; ++i)
                #pragma unroll
                for (int j = 0; j < 8; ++j)
                    acc[i][j] = fmaf(av[i], bv[j], acc[i][j]);
        }
        if (more) {
            int nxt = cur ^ 1;
            As[nxt][aCol + 0][aRow] = an.x;
            As[nxt][aCol + 1][aRow] = an.y;
            As[nxt][aCol + 2][aRow] = an.z;
            As[nxt][aCol + 3][aRow] = an.w;
            *(float4*)&Bs[nxt][bRow][bCol] = bn;
            __syncthreads();
        }
    }

    #pragma unroll
    for (int ii = 0; ii < 8; ++ii) {
        int r = by + ((ii < 4) ? (ty * 4 + ii) : (64 + ty * 4 + ii - 4));
        float* Crow = C + (size_t)r * ldc + bx;
        int c0 = tx * 4, c1 = 64 + tx * 4;
        float4 v0 = make_float4(acc[ii][0], acc[ii][1], acc[ii][2], acc[ii][3]);
        float4 v1 = make_float4(acc[ii][4], acc[ii][5], acc[ii][6], acc[ii][7]);
        if (epi == 1) {
            const float* Erow = extra + (size_t)r * ldc + bx;
            float4 e0 = *(const float4*)(Erow + c0);
            float4 e1 = *(const float4*)(Erow + c1);
            v0.x += e0.x; v0.y += e0.y; v0.z += e0.z; v0.w += e0.w;
            v1.x += e1.x; v1.y += e1.y; v1.z += e1.z; v1.w += e1.w;
        } else if (epi == 2) {
            const float* bias = extra + bx;
            v0.x = softplus_f(v0.x + bias[c0 + 0]);
            v0.y = softplus_f(v0.y + bias[c0 + 1]);
            v0.z = softplus_f(v0.z + bias[c0 + 2]);
            v0.w = softplus_f(v0.w + bias[c0 + 3]);
            v1.x = softplus_f(v1.x + bias[c1 + 0]);
            v1.y = softplus_f(v1.y + bias[c1 + 1]);
            v1.z = softplus_f(v1.z + bias[c1 + 2]);
            v1.w = softplus_f(v1.w + bias[c1 + 3]);
        }
        *(float4*)(Crow + c0) = v0;
        *(float4*)(Crow + c1) = v1;
    }
}

// ---------------- depthwise conv along d_inner + SiLU ----------------
// xconv[l][d] = silu(conv_b[l] + sum_{k=0..3} conv_w[k][0][l] * x[l][d+k-1])
__global__ void conv_silu_kernel(const float* __restrict__ cw,
                                 const float* __restrict__ cb) {
    int l = blockIdx.x;
    int t = threadIdx.x;
    __shared__ float xs[DI];
    const float4* src = (const float4*)(g_xres + (size_t)l * 2 * DI);  // x half
    float4* dst4 = (float4*)xs;
    for (int i = t; i < DI / 4; i += 256) dst4[i] = src[i];
    __syncthreads();
    float w0 = cw[l], w1 = cw[DI + l], w2 = cw[2 * DI + l], w3 = cw[3 * DI + l];
    float b = cb[l];
    for (int d = t; d < DI; d += 256) {
        float xm1 = (d > 0) ? xs[d - 1] : 0.f;
        float x0  = xs[d];
        float xp1 = (d < DI - 1) ? xs[d + 1] : 0.f;
        float xp2 = (d < DI - 2) ? xs[d + 2] : 0.f;
        float v = b + w0 * xm1 + w1 * x0 + w2 * xp1 + w3 * xp2;
        g_xconv[(size_t)l * DI + d] = v * (1.f / (1.f + __expf(-v)));
    }
}

// ---------------- x_proj: [2048x1024] @ [1024x96] -> g_xdbl (stride 96) ----------------
// block = 192 threads (r2 = t/96 in {0,1}, c = t%96), 16 rows per block, 8 rows/thread
__global__ void __launch_bounds__(192) xproj_kernel(const float* __restrict__ W) {
    __shared__ float4 us4[16 * 32];   // [row][kchunk4] of u tile, 128 K per stage
    int t  = threadIdx.x;
    int l0 = blockIdx.x * 16;
    int c  = t % 96;
    int r2 = t / 96;                  // uniform per warp (96 = 3 warps)
    float acc[8];
    #pragma unroll
    for (int i = 0; i < 8; ++i) acc[i] = 0.f;

    for (int k0 = 0; k0 < DM; k0 += 128) {
        __syncthreads();
        for (int i = t; i < 512; i += 192) {
            int r = i >> 5, q = i & 31;
            us4[i] = *(const float4*)(g_u + (size_t)(l0 + r) * DM + k0 + q * 4);
        }
        __syncthreads();
        #pragma unroll 4
        for (int kk4 = 0; kk4 < 32; ++kk4) {
            int k = k0 + kk4 * 4;
            float w0 = W[(size_t)(k + 0) * 96 + c];
            float w1 = W[(size_t)(k + 1) * 96 + c];
            float w2 = W[(size_t)(k + 2) * 96 + c];
            float w3 = W[(size_t)(k + 3) * 96 + c];
            #pragma unroll
            for (int ri = 0; ri < 8; ++ri) {
                float4 u4 = us4[(r2 * 8 + ri) * 32 + kk4];
                acc[ri] += w0 * u4.x + w1 * u4.y + w2 * u4.z + w3 * u4.w;
            }
        }
    }
    #pragma unroll
    for (int ri = 0; ri < 8; ++ri)
        g_xdbl[(size_t)(l0 + r2 * 8 + ri) * 96 + c] = acc[ri];
}

// ---------------- selective scan ----------------
// one thread per (d, n); 16 channels per block; chunked smem staging;
// fuses y = (scan + x*D) * silu(res)
__global__ void __launch_bounds__(256) scan_kernel(const float* __restrict__ A_log,
                                                   const float* __restrict__ Dp) {
    __shared__ float sdelta[16][16], sx[16][16], sB[16][16], sC[16][16], sres[16][16];
    int t  = threadIdx.x;
    int g  = t >> 4;      // channel within block
    int n  = t & 15;      // state index
    int d0 = blockIdx.x * 16;
    int d  = d0 + g;

    float a  = -expf(A_log[(size_t)d * DS + n]);
    float Dd = Dp[d];
    float h  = 0.f;

    for (int l0 = 0; l0 < LSEQ; l0 += 16) {
        // stage 16 timesteps (reuse (g,n) as (row,col) of the staging tile)
        sdelta[g][n] = g_delta[(size_t)(l0 + g) * DI + d0 + n];
        sx[g][n]     = g_xconv[(size_t)(l0 + g) * DI + d0 + n];
        sres[g][n]   = g_xres[(size_t)(l0 + g) * 2 * DI + DI + d0 + n];
        sB[g][n]     = g_xdbl[(size_t)(l0 + g) * 96 + 64 + n];
        sC[g][n]     = g_xdbl[(size_t)(l0 + g) * 96 + 80 + n];
        __syncthreads();
        #pragma unroll
        for (int i = 0; i < 16; ++i) {
            float dlt = sdelta[i][g];
            float xv  = sx[i][g];
            float dA  = __expf(dlt * a);
            h = fmaf(dA, h, dlt * sB[i][n] * xv);
            float yp = h * sC[i][n];
            yp += __shfl_xor_sync(0xffffffffu, yp, 8, 16);
            yp += __shfl_xor_sync(0xffffffffu, yp, 4, 16);
            yp += __shfl_xor_sync(0xffffffffu, yp, 2, 16);
            yp += __shfl_xor_sync(0xffffffffu, yp, 1, 16);
            if (n == 0) {
                float r   = sres[i][g];
                float sil = r * (1.f / (1.f + __expf(-r)));
                g_y[(size_t)(l0 + i) * DI + d] = (yp + xv * Dd) * sil;
            }
        }
        __syncthreads();
    }
}

// ---------------- launch ----------------
extern "C" void kernel_launch(void* const* d_in, const int* in_sizes, int n_in,
                              void* d_out, int out_size) {
    const float* inputs     = (const float*)d_in[0];
    const float* norm_scale = (const float*)d_in[1];
    const float* in_proj_w  = (const float*)d_in[2];
    const float* conv_w     = (const float*)d_in[3];
    const float* conv_b     = (const float*)d_in[4];
    const float* x_proj_w   = (const float*)d_in[5];
    const float* dt_proj_w  = (const float*)d_in[6];
    const float* dt_proj_b  = (const float*)d_in[7];
    const float* out_proj_w = (const float*)d_in[8];
    const float* A_log      = (const float*)d_in[9];
    const float* Dvec       = (const float*)d_in[10];
    float* out = (float*)d_out;

    void *p_u, *p_xres, *p_xdbl, *p_delta, *p_y;
    cudaGetSymbolAddress(&p_u, g_u);
    cudaGetSymbolAddress(&p_xres, g_xres);
    cudaGetSymbolAddress(&p_xdbl, g_xdbl);
    cudaGetSymbolAddress(&p_delta, g_delta);
    cudaGetSymbolAddress(&p_y, g_y);

    // 1) RMSNorm
    rmsnorm_kernel<<<LSEQ, 256>>>(inputs, norm_scale);

    // 2) G1: u @ in_proj_w -> xres [2048 x 4096]
    sgemm128<<<dim3(4096 / 128, LSEQ / 128), 256>>>(
        (const float*)p_u, DM, in_proj_w, 2 * DI, (float*)p_xres, 2 * DI,
        nullptr, DM, 0);

    // 3) conv (along d) + silu -> xconv
    conv_silu_kernel<<<LSEQ, 256>>>(conv_w, conv_b);

    // 4) G2: u @ x_proj_w -> xdbl [2048 x 96]
    xproj_kernel<<<LSEQ / 16, 192>>>(x_proj_w);

    // 5) G3: delta_r @ dt_proj_w + bias, softplus -> delta [2048 x 2048]
    sgemm128<<<dim3(DI / 128, LSEQ / 128), 256>>>(
        (const float*)p_xdbl, 96, dt_proj_w, DI, (float*)p_delta, DI,
        dt_proj_b, 64, 2);

    // 6) selective scan (+ x*D, * silu(res)) -> y
    scan_kernel<<<DI / 16, 256>>>(A_log, Dvec);

    // 7) G4: y @ out_proj_w + inputs -> out [2048 x 1024]
    sgemm128<<<dim3(DM / 128, LSEQ / 128), 256>>>(
        (const float*)p_y, DI, out_proj_w, DM, out, DM,
        inputs, DI, 1);
}

// round 3
// speedup vs baseline: 1.0898x; 1.0898x over previous
#include <cuda_runtime.h>
#include <cuda_bf16.h>
#include <cstdint>

#define LSEQ 2048
#define DM   1024
#define DI   2048
#define DS   16

// ---------------- scratch ----------------
__device__ float g_u[LSEQ * DM];
__device__ float g_xres[LSEQ * 2 * DI];
__device__ float g_xconv[LSEQ * DI];
__device__ float g_xdbl[LSEQ * 96];
__device__ float g_delta[LSEQ * DI];
__device__ float g_y[LSEQ * DI];

__device__ __forceinline__ float softplus_f(float x) {
    return fmaxf(x, 0.f) + log1pf(__expf(-fabsf(x)));
}

// ---------------- mma.sync / ldmatrix helpers (sm_80+ portable) ----------------
__device__ __forceinline__ uint32_t smem_to_u32(const void* p) {
    uint32_t a;
    asm("{ .reg .u64 t; cvta.to.shared.u64 t, %1; cvt.u32.u64 %0, t; }" : "=r"(a) : "l"(p));
    return a;
}
__device__ __forceinline__ void ldsm4(uint32_t* r, uint32_t addr) {
    asm volatile("ldmatrix.sync.aligned.m8n8.x4.shared.b16 {%0,%1,%2,%3}, [%4];"
                 : "=r"(r[0]), "=r"(r[1]), "=r"(r[2]), "=r"(r[3]) : "r"(addr));
}
__device__ __forceinline__ void ldsm2(uint32_t* r, uint32_t addr) {
    asm volatile("ldmatrix.sync.aligned.m8n8.x2.shared.b16 {%0,%1}, [%2];"
                 : "=r"(r[0]), "=r"(r[1]) : "r"(addr));
}
__device__ __forceinline__ void mma_bf16(float* c, const uint32_t* a, const uint32_t* b) {
    asm volatile("mma.sync.aligned.m16n8k16.row.col.f32.bf16.bf16.f32 "
                 "{%0,%1,%2,%3}, {%4,%5,%6,%7}, {%8,%9}, {%0,%1,%2,%3};"
                 : "+f"(c[0]), "+f"(c[1]), "+f"(c[2]), "+f"(c[3])
                 : "r"(a[0]), "r"(a[1]), "r"(a[2]), "r"(a[3]), "r"(b[0]), "r"(b[1]));
}

// fp32 -> bf16 hi/lo split
__device__ __forceinline__ void split1(float x, unsigned short& h, unsigned short& l) {
    __nv_bfloat16 hb = __float2bfloat16_rn(x);
    h = __bfloat16_as_ushort(hb);
    l = __bfloat16_as_ushort(__float2bfloat16_rn(x - __bfloat162float(hb)));
}
__device__ __forceinline__ void split2(float x, float y, uint32_t& hi, uint32_t& lo) {
    unsigned short hx, lx, hy, ly;
    split1(x, hx, lx);
    split1(y, hy, ly);
    hi = (uint32_t)hx | ((uint32_t)hy << 16);
    lo = (uint32_t)lx | ((uint32_t)ly << 16);
}

// ---------------- split-bf16 HMMA GEMM: C[M x N] = A[M x K] * B[K x N] ----------------
// tile 128x128xBK32, 8 warps (2x4), warp tile 64x32
// EPI 0: store. EPI 1: += extra[m*lde+col]. EPI 2: softplus(acc + extra[col]).
template <int EPI>
__global__ void __launch_bounds__(256, 1) tc_gemm(
    const float* __restrict__ A, int lda,
    const float* __restrict__ Bm, int ldb,
    float* __restrict__ C, int ldc,
    const float* __restrict__ extra, int lde,
    int K, int n_real)
{
    extern __shared__ char sm[];
    constexpr int AP   = 40;              // padded bf16 cols per row (80B stride)
    constexpr int ABYT = 128 * AP * 2;    // 10240 bytes per matrix plane
    constexpr int STG  = 4 * ABYT;        // Ah | Al | Bh | Bl

    int tid = threadIdx.x, wid = tid >> 5, lane = tid & 31;
    int bx = blockIdx.x * 128, by = blockIdx.y * 128;
    int wm = (wid >> 2) * 64, wn = (wid & 3) * 32;

    float acc[4][4][4];
    #pragma unroll
    for (int i = 0; i < 4; ++i)
        #pragma unroll
        for (int j = 0; j < 4; ++j)
            #pragma unroll
            for (int r = 0; r < 4; ++r) acc[i][j][r] = 0.f;

    uint32_t smbase = smem_to_u32(sm);
    int T = K >> 5;

    float4 pa[4], pb[4];
    // ---- gmem tile load into regs ----
    auto load_regs = [&](int t) {
        int kb = t << 5;
        #pragma unroll
        for (int i = 0; i < 4; ++i) {
            int pid = i * 256 + tid;
            int row = pid >> 3, colq = (pid & 7) << 2;
            pa[i] = *(const float4*)(A + (size_t)(by + row) * lda + kb + colq);
        }
        #pragma unroll
        for (int i = 0; i < 4; ++i) {
            int pid = i * 256 + tid;
            int k = pid >> 5, colq = (pid & 31) << 2;
            if (bx + colq < n_real)
                pb[i] = *(const float4*)(Bm + (size_t)(kb + k) * ldb + bx + colq);
            else
                pb[i] = make_float4(0.f, 0.f, 0.f, 0.f);
        }
    };
    // ---- regs -> split bf16 smem ----
    auto store_smem = [&](int buf) {
        char* Ah = sm + buf * STG;
        char* Al = Ah + ABYT;
        char* Bh = Al + ABYT;
        char* Bl = Bh + ABYT;
        #pragma unroll
        for (int i = 0; i < 4; ++i) {
            int pid = i * 256 + tid;
            int row = pid >> 3, colq = (pid & 7) << 2;
            uint32_t h0, l0, h1, l1;
            split2(pa[i].x, pa[i].y, h0, l0);
            split2(pa[i].z, pa[i].w, h1, l1);
            int off = (row * AP + colq) * 2;
            *(uint2*)(Ah + off) = make_uint2(h0, h1);
            *(uint2*)(Al + off) = make_uint2(l0, l1);
        }
        #pragma unroll
        for (int i = 0; i < 4; ++i) {
            int pid = i * 256 + tid;
            int k = pid >> 5, colq = (pid & 31) << 2;
            float v[4] = {pb[i].x, pb[i].y, pb[i].z, pb[i].w};
            #pragma unroll
            for (int j = 0; j < 4; ++j) {
                unsigned short h, l;
                split1(v[j], h, l);
                int off = ((colq + j) * AP + k) * 2;
                *(unsigned short*)(Bh + off) = h;
                *(unsigned short*)(Bl + off) = l;
            }
        }
    };
    // ---- MMA block on one smem buffer ----
    auto compute = [&](int buf) {
        uint32_t sA  = smbase + buf * STG;
        uint32_t sAl = sA + ABYT;
        uint32_t sBh = sA + 2 * ABYT;
        uint32_t sBl = sA + 3 * ABYT;
        #pragma unroll
        for (int kk = 0; kk < 2; ++kk) {
            int k0 = kk * 16;
            uint32_t ah[4][4], al[4][4], bh[4][2], bl[4][2];
            int arow = wm + (lane & 15);
            int acol = k0 + ((lane >> 4) << 3);
            #pragma unroll
            for (int mt = 0; mt < 4; ++mt) {
                uint32_t off = (uint32_t)(((arow + mt * 16) * AP + acol) * 2);
                ldsm4(ah[mt], sA + off);
                ldsm4(al[mt], sAl + off);
            }
            int brow = wn + (lane & 7);
            int bcol = k0 + ((lane >> 3) & 1) * 8;
            #pragma unroll
            for (int nt = 0; nt < 4; ++nt) {
                uint32_t off = (uint32_t)(((brow + nt * 8) * AP + bcol) * 2);
                ldsm2(bh[nt], sBh + off);
                ldsm2(bl[nt], sBl + off);
            }
            #pragma unroll
            for (int mt = 0; mt < 4; ++mt)
                #pragma unroll
                for (int nt = 0; nt < 4; ++nt) {
                    mma_bf16(acc[mt][nt], ah[mt], bh[nt]);
                    mma_bf16(acc[mt][nt], ah[mt], bl[nt]);
                    mma_bf16(acc[mt][nt], al[mt], bh[nt]);
                }
        }
    };

    load_regs(0);
    store_smem(0);
    __syncthreads();
    for (int t = 0; t < T; ++t) {
        int cur = t & 1;
        bool more = (t + 1 < T);
        if (more) load_regs(t + 1);
        compute(cur);
        if (more) {
            store_smem(cur ^ 1);
            __syncthreads();
        }
    }

    // ---- epilogue ----
    #pragma unroll
    for (int mt = 0; mt < 4; ++mt) {
        #pragma unroll
        for (int nt = 0; nt < 4; ++nt) {
            int row0 = by + wm + mt * 16 + (lane >> 2);
            int col  = bx + wn + nt * 8 + (lane & 3) * 2;
            if (col < n_real) {
                float* a = acc[mt][nt];
                float2 v0 = make_float2(a[0], a[1]);
                float2 v1 = make_float2(a[2], a[3]);
                if (EPI == 1) {
                    float2 e0 = *(const float2*)(extra + (size_t)row0 * lde + col);
                    float2 e1 = *(const float2*)(extra + (size_t)(row0 + 8) * lde + col);
                    v0.x += e0.x; v0.y += e0.y;
                    v1.x += e1.x; v1.y += e1.y;
                } else if (EPI == 2) {
                    float b0 = extra[col], b1 = extra[col + 1];
                    v0.x = softplus_f(v0.x + b0);
                    v0.y = softplus_f(v0.y + b1);
                    v1.x = softplus_f(v1.x + b0);
                    v1.y = softplus_f(v1.y + b1);
                }
                *(float2*)(C + (size_t)row0 * ldc + col)       = v0;
                *(float2*)(C + (size_t)(row0 + 8) * ldc + col) = v1;
            }
        }
    }
}

// ---------------- RMSNorm ----------------
__global__ void rmsnorm_kernel(const float* __restrict__ in,
                               const float* __restrict__ scale) {
    int l = blockIdx.x;
    int t = threadIdx.x;
    const float* row = in + (size_t)l * DM;
    float s = 0.f;
    for (int i = t; i < DM; i += 256) { float v = row[i]; s += v * v; }
    __shared__ float red[256];
    red[t] = s; __syncthreads();
    for (int o = 128; o > 0; o >>= 1) {
        if (t < o) red[t] += red[t + o];
        __syncthreads();
    }
    float inv = rsqrtf(red[0] * (1.f / DM) + 1e-6f);
    for (int i = t; i < DM; i += 256)
        g_u[(size_t)l * DM + i] = row[i] * inv * scale[i];
}

// ---------------- depthwise conv along d_inner + SiLU ----------------
__global__ void conv_silu_kernel(const float* __restrict__ cw,
                                 const float* __restrict__ cb) {
    int l = blockIdx.x;
    int t = threadIdx.x;
    __shared__ float xs[DI];
    const float4* src = (const float4*)(g_xres + (size_t)l * 2 * DI);
    float4* dst4 = (float4*)xs;
    for (int i = t; i < DI / 4; i += 256) dst4[i] = src[i];
    __syncthreads();
    float w0 = cw[l], w1 = cw[DI + l], w2 = cw[2 * DI + l], w3 = cw[3 * DI + l];
    float b = cb[l];
    for (int d = t; d < DI; d += 256) {
        float xm1 = (d > 0) ? xs[d - 1] : 0.f;
        float x0  = xs[d];
        float xp1 = (d < DI - 1) ? xs[d + 1] : 0.f;
        float xp2 = (d < DI - 2) ? xs[d + 2] : 0.f;
        float v = b + w0 * xm1 + w1 * x0 + w2 * xp1 + w3 * xp2;
        g_xconv[(size_t)l * DI + d] = v * (1.f / (1.f + __expf(-v)));
    }
}

// ---------------- selective scan (reg-prefetched chunks) ----------------
__global__ void __launch_bounds__(256) scan_kernel(const float* __restrict__ A_log,
                                                   const float* __restrict__ Dp) {
    __shared__ float sdelta[16][16], sx[16][16], sB[16][16], sC[16][16], sres[16][16];
    int t = threadIdx.x;
    int g = t >> 4;
    int n = t & 15;
    int d0 = blockIdx.x * 16;
    int d  = d0 + g;

    float a  = -expf(A_log[(size_t)d * DS + n]);
    float Dd = Dp[d];
    float h  = 0.f;

    float pd = g_delta[(size_t)g * DI + d0 + n];
    float px = g_xconv[(size_t)g * DI + d0 + n];
    float pr = g_xres[(size_t)g * 2 * DI + DI + d0 + n];
    float pB = g_xdbl[(size_t)g * 96 + 64 + n];
    float pC = g_xdbl[(size_t)g * 96 + 80 + n];

    for (int l0 = 0; l0 < LSEQ; l0 += 16) {
        sdelta[g][n] = pd; sx[g][n] = px; sres[g][n] = pr; sB[g][n] = pB; sC[g][n] = pC;
        __syncthreads();
        if (l0 + 16 < LSEQ) {
            int l = l0 + 16 + g;
            pd = g_delta[(size_t)l * DI + d0 + n];
            px = g_xconv[(size_t)l * DI + d0 + n];
            pr = g_xres[(size_t)l * 2 * DI + DI + d0 + n];
            pB = g_xdbl[(size_t)l * 96 + 64 + n];
            pC = g_xdbl[(size_t)l * 96 + 80 + n];
        }
        #pragma unroll
        for (int i = 0; i < 16; ++i) {
            float dlt = sdelta[i][g];
            float xv  = sx[i][g];
            float dA  = __expf(dlt * a);
            h = fmaf(dA, h, dlt * sB[i][n] * xv);
            float yp = h * sC[i][n];
            yp += __shfl_xor_sync(0xffffffffu, yp, 8, 16);
            yp += __shfl_xor_sync(0xffffffffu, yp, 4, 16);
            yp += __shfl_xor_sync(0xffffffffu, yp, 2, 16);
            yp += __shfl_xor_sync(0xffffffffu, yp, 1, 16);
            if (n == 0) {
                float r = sres[i][g];
                g_y[(size_t)(l0 + i) * DI + d] = (yp + xv * Dd) * (r / (1.f + __expf(-r)));
            }
        }
        __syncthreads();
    }
}

// ---------------- launch ----------------
extern "C" void kernel_launch(void* const* d_in, const int* in_sizes, int n_in,
                              void* d_out, int out_size) {
    const float* inputs     = (const float*)d_in[0];
    const float* norm_scale = (const float*)d_in[1];
    const float* in_proj_w  = (const float*)d_in[2];
    const float* conv_w     = (const float*)d_in[3];
    const float* conv_b     = (const float*)d_in[4];
    const float* x_proj_w   = (const float*)d_in[5];
    const float* dt_proj_w  = (const float*)d_in[6];
    const float* dt_proj_b  = (const float*)d_in[7];
    const float* out_proj_w = (const float*)d_in[8];
    const float* A_log      = (const float*)d_in[9];
    const float* Dvec       = (const float*)d_in[10];
    float* out = (float*)d_out;

    void *p_u, *p_xres, *p_xdbl, *p_delta, *p_y;
    cudaGetSymbolAddress(&p_u, g_u);
    cudaGetSymbolAddress(&p_xres, g_xres);
    cudaGetSymbolAddress(&p_xdbl, g_xdbl);
    cudaGetSymbolAddress(&p_delta, g_delta);
    cudaGetSymbolAddress(&p_y, g_y);

    const int SMEM = 2 * 4 * 128 * 40 * 2;  // 81920 bytes (2 stages)
    cudaFuncSetAttribute(tc_gemm<0>, cudaFuncAttributeMaxDynamicSharedMemorySize, SMEM);
    cudaFuncSetAttribute(tc_gemm<1>, cudaFuncAttributeMaxDynamicSharedMemorySize, SMEM);
    cudaFuncSetAttribute(tc_gemm<2>, cudaFuncAttributeMaxDynamicSharedMemorySize, SMEM);

    // 1) RMSNorm
    rmsnorm_kernel<<<LSEQ, 256>>>(inputs, norm_scale);

    // 2) G1: u @ in_proj_w -> xres [2048 x 4096]
    tc_gemm<0><<<dim3(32, 16), 256, SMEM>>>(
        (const float*)p_u, DM, in_proj_w, 2 * DI, (float*)p_xres, 2 * DI,
        nullptr, 0, DM, 2 * DI);

    // 3) conv (along d) + silu -> xconv
    conv_silu_kernel<<<LSEQ, 256>>>(conv_w, conv_b);

    // 4) G2: u @ x_proj_w -> xdbl [2048 x 96] (N tile padded to 128)
    tc_gemm<0><<<dim3(1, 16), 256, SMEM>>>(
        (const float*)p_u, DM, x_proj_w, 96, (float*)p_xdbl, 96,
        nullptr, 0, DM, 96);

    // 5) G3: delta_r @ dt_proj_w + bias, softplus -> delta [2048 x 2048]
    tc_gemm<2><<<dim3(16, 16), 256, SMEM>>>(
        (const float*)p_xdbl, 96, dt_proj_w, DI, (float*)p_delta, DI,
        dt_proj_b, 0, 64, DI);

    // 6) selective scan -> y
    scan_kernel<<<DI / 16, 256>>>(A_log, Dvec);

    // 7) G4: y @ out_proj_w + inputs -> out [2048 x 1024]
    tc_gemm<1><<<dim3(8, 16), 256, SMEM>>>(
        (const float*)p_y, DI, out_proj_w, DM, out, DM,
        inputs, DM, DI, DM);
}

// round 5
// speedup vs baseline: 1.6636x; 1.5266x over previous
#include <cuda_runtime.h>
#include <cuda_bf16.h>
#include <cstdint>

#define LSEQ 2048
#define DM   1024
#define DI   2048
#define DS   16

// ---------------- scratch ----------------
__device__ float g_xres[LSEQ * 2 * DI];           // G1 out (x | res), fp32
__device__ float g_xconv[LSEQ * DI];              // conv+silu, fp32
__device__ float g_xdbl[LSEQ * 96];               // x_proj out, fp32 (B,C for scan)
__device__ float g_delta[LSEQ * DI];              // softplus delta, fp32
__device__ __nv_bfloat16 g_u_hi[LSEQ * DM],  g_u_lo[LSEQ * DM];
__device__ __nv_bfloat16 g_dr_hi[LSEQ * 64], g_dr_lo[LSEQ * 64];
__device__ __nv_bfloat16 g_y_hi[LSEQ * DI],  g_y_lo[LSEQ * DI];
// weight planes
__device__ __nv_bfloat16 g_w1h[DM * 2 * DI], g_w1l[DM * 2 * DI];
__device__ __nv_bfloat16 g_w2h[DM * 96],     g_w2l[DM * 96];
__device__ __nv_bfloat16 g_w3h[64 * DI],     g_w3l[64 * DI];
__device__ __nv_bfloat16 g_w4h[DI * DM],     g_w4l[DI * DM];

__device__ __forceinline__ float softplus_f(float x) {
    return fmaxf(x, 0.f) + log1pf(__expf(-fabsf(x)));
}
__device__ __forceinline__ uint32_t smem_to_u32(const void* p) {
    uint32_t a;
    asm("{ .reg .u64 t; cvta.to.shared.u64 t, %1; cvt.u32.u64 %0, t; }" : "=r"(a) : "l"(p));
    return a;
}
__device__ __forceinline__ void ldsm4(uint32_t* r, uint32_t addr) {
    asm volatile("ldmatrix.sync.aligned.m8n8.x4.shared.b16 {%0,%1,%2,%3}, [%4];"
                 : "=r"(r[0]), "=r"(r[1]), "=r"(r[2]), "=r"(r[3]) : "r"(addr));
}
__device__ __forceinline__ void ldsm4t(uint32_t* r, uint32_t addr) {
    asm volatile("ldmatrix.sync.aligned.m8n8.x4.trans.shared.b16 {%0,%1,%2,%3}, [%4];"
                 : "=r"(r[0]), "=r"(r[1]), "=r"(r[2]), "=r"(r[3]) : "r"(addr));
}
__device__ __forceinline__ void mma_bf16(float* c, const uint32_t* a, const uint32_t* b) {
    asm volatile("mma.sync.aligned.m16n8k16.row.col.f32.bf16.bf16.f32 "
                 "{%0,%1,%2,%3}, {%4,%5,%6,%7}, {%8,%9}, {%0,%1,%2,%3};"
                 : "+f"(c[0]), "+f"(c[1]), "+f"(c[2]), "+f"(c[3])
                 : "r"(a[0]), "r"(a[1]), "r"(a[2]), "r"(a[3]), "r"(b[0]), "r"(b[1]));
}
__device__ __forceinline__ void cp16(uint32_t dst, const void* src, int sz) {
    asm volatile("cp.async.cg.shared.global [%0], [%1], 16, %2;" :: "r"(dst), "l"(src), "r"(sz));
}
#define CP_COMMIT() asm volatile("cp.async.commit_group;" ::: "memory")
#define CP_WAIT1()  asm volatile("cp.async.wait_group 1;" ::: "memory")

__device__ __forceinline__ void split1(float x, __nv_bfloat16& h, __nv_bfloat16& l) {
    h = __float2bfloat16_rn(x);
    l = __float2bfloat16_rn(x - __bfloat162float(h));
}

// ---------------- fp32 -> bf16 hi/lo plane converter ----------------
__global__ void convert_split(const float* __restrict__ src,
                              __nv_bfloat16* __restrict__ hi,
                              __nv_bfloat16* __restrict__ lo, int n4) {
    int i = blockIdx.x * blockDim.x + threadIdx.x;
    if (i >= n4) return;
    float4 v = ((const float4*)src)[i];
    __nv_bfloat16 h[4], l[4];
    split1(v.x, h[0], l[0]); split1(v.y, h[1], l[1]);
    split1(v.z, h[2], l[2]); split1(v.w, h[3], l[3]);
    ((uint2*)hi)[i] = make_uint2(
        (uint32_t)__bfloat16_as_ushort(h[0]) | ((uint32_t)__bfloat16_as_ushort(h[1]) << 16),
        (uint32_t)__bfloat16_as_ushort(h[2]) | ((uint32_t)__bfloat16_as_ushort(h[3]) << 16));
    ((uint2*)lo)[i] = make_uint2(
        (uint32_t)__bfloat16_as_ushort(l[0]) | ((uint32_t)__bfloat16_as_ushort(l[1]) << 16),
        (uint32_t)__bfloat16_as_ushort(l[2]) | ((uint32_t)__bfloat16_as_ushort(l[3]) << 16));
}

// ---------------- split-bf16 HMMA GEMM, cp.async 3-stage ----------------
// tile 128x128 x BK32; 8 warps (2x4), warp 64x32.
// A smem: [128][40] bf16 (80B rows), 2 planes. B smem: [32][136] bf16 (272B rows), 2 planes.
// epi: 0 plain, 1 +extra[r*lde+c], 2 softplus(acc+extra[c]), 3 plain + dr bf16 planes (c<64)
__global__ void __launch_bounds__(256, 1) hgemm(
    const __nv_bfloat16* __restrict__ Ah, const __nv_bfloat16* __restrict__ Al, int lda,
    const __nv_bfloat16* Bh, const __nv_bfloat16* Bl, int ldb,
    float* C, int ldc, const float* __restrict__ extra, int lde,
    int K, int n_real, int epi, int nsplit,
    const __nv_bfloat16* B2h, const __nv_bfloat16* B2l, int ldb2,
    float* C2, int ldc2, int n2, int epi2)
{
    extern __shared__ char sm[];
    constexpr int APL = 10240;            // A plane bytes (128*80)
    constexpr int BPL = 8704;             // B plane bytes (32*272)
    constexpr int STG = 2 * APL + 2 * BPL;  // 37888 per stage

    int tid = threadIdx.x, wid = tid >> 5, lane = tid & 31;
    int bxi = blockIdx.x;
    int bx;
    if (bxi >= nsplit) {
        Bh = B2h; Bl = B2l; ldb = ldb2; C = C2; ldc = ldc2;
        n_real = n2; epi = epi2; bx = (bxi - nsplit) * 128;
    } else {
        bx = bxi * 128;
    }
    int by = blockIdx.y * 128;
    int wm = (wid >> 2) * 64, wn = (wid & 3) * 32;
    uint32_t smb = smem_to_u32(sm);

    float acc[4][4][4];
    #pragma unroll
    for (int i = 0; i < 4; ++i)
        #pragma unroll
        for (int j = 0; j < 4; ++j)
            #pragma unroll
            for (int r = 0; r < 4; ++r) acc[i][j][r] = 0.f;

    int T = K >> 5;

    auto load_stage = [&](int s) {
        uint32_t base = smb + (s % 3) * STG;
        int kb = s << 5;
        // A: 2 planes x 128 rows x 4 chunks(16B)
        #pragma unroll
        for (int i = 0; i < 4; ++i) {
            int pid = i * 256 + tid;
            int pl = pid >> 9, rem = pid & 511;
            int row = rem >> 2, ch = rem & 3;
            const __nv_bfloat16* src = (pl ? Al : Ah) + (size_t)(by + row) * lda + kb + ch * 8;
            cp16(base + pl * APL + row * 80 + ch * 16, src, 16);
        }
        // B: 2 planes x 32 k-rows x 16 chunks(16B)
        #pragma unroll
        for (int i = 0; i < 4; ++i) {
            int pid = i * 256 + tid;
            int pl = pid >> 9, rem = pid & 511;
            int k = rem >> 4, ch = rem & 15;
            int col = bx + ch * 8;
            bool v = col < n_real;
            const __nv_bfloat16* src = v ? ((pl ? Bl : Bh) + (size_t)(kb + k) * ldb + col)
                                         : Bh;
            cp16(base + 2 * APL + pl * BPL + k * 272 + ch * 16, src, v ? 16 : 0);
        }
    };

    load_stage(0); CP_COMMIT();
    if (T > 1) { load_stage(1); }
    CP_COMMIT();

    for (int s = 0; s < T; ++s) {
        CP_WAIT1();
        __syncthreads();
        if (s + 2 < T) load_stage(s + 2);
        CP_COMMIT();

        uint32_t bA  = smb + (s % 3) * STG;
        uint32_t bAl = bA + APL;
        uint32_t bBh = bA + 2 * APL;
        uint32_t bBl = bBh + BPL;
        #pragma unroll
        for (int kk = 0; kk < 2; ++kk) {
            int k0 = kk * 16;
            uint32_t ah[4][4], al[4][4], bh[2][4], bl[2][4];
            int arow = wm + (lane & 15);
            int acol = k0 + ((lane >> 4) << 3);
            #pragma unroll
            for (int mt = 0; mt < 4; ++mt) {
                uint32_t off = (uint32_t)((arow + mt * 16) * 80 + acol * 2);
                ldsm4(ah[mt], bA + off);
                ldsm4(al[mt], bAl + off);
            }
            int bk = k0 + (lane & 15);
            #pragma unroll
            for (int ns = 0; ns < 2; ++ns) {
                int bn = wn + ns * 16 + ((lane >> 4) << 3);
                uint32_t off = (uint32_t)(bk * 272 + bn * 2);
                ldsm4t(bh[ns], bBh + off);
                ldsm4t(bl[ns], bBl + off);
            }
            #pragma unroll
            for (int mt = 0; mt < 4; ++mt)
                #pragma unroll
                for (int nt = 0; nt < 4; ++nt) {
                    const uint32_t* bph = &bh[nt >> 1][(nt & 1) * 2];
                    const uint32_t* bpl = &bl[nt >> 1][(nt & 1) * 2];
                    mma_bf16(acc[mt][nt], ah[mt], bph);
                    mma_bf16(acc[mt][nt], ah[mt], bpl);
                    mma_bf16(acc[mt][nt], al[mt], bph);
                }
        }
        __syncthreads();
    }

    // ---- epilogue ----
    #pragma unroll
    for (int mt = 0; mt < 4; ++mt) {
        #pragma unroll
        for (int nt = 0; nt < 4; ++nt) {
            int row0 = by + wm + mt * 16 + (lane >> 2);
            int col  = bx + wn + nt * 8 + (lane & 3) * 2;
            if (col < n_real) {
                float* a = acc[mt][nt];
                float2 v0 = make_float2(a[0], a[1]);
                float2 v1 = make_float2(a[2], a[3]);
                if (epi == 1) {
                    float2 e0 = *(const float2*)(extra + (size_t)row0 * lde + col);
                    float2 e1 = *(const float2*)(extra + (size_t)(row0 + 8) * lde + col);
                    v0.x += e0.x; v0.y += e0.y;
                    v1.x += e1.x; v1.y += e1.y;
                } else if (epi == 2) {
                    float b0 = extra[col], b1 = extra[col + 1];
                    v0.x = softplus_f(v0.x + b0);
                    v0.y = softplus_f(v0.y + b1);
                    v1.x = softplus_f(v1.x + b0);
                    v1.y = softplus_f(v1.y + b1);
                }
                *(float2*)(C + (size_t)row0 * ldc + col)       = v0;
                *(float2*)(C + (size_t)(row0 + 8) * ldc + col) = v1;
                if (epi == 3 && col < 64) {
                    __nv_bfloat16 h, l;
                    split1(v0.x, h, l); g_dr_hi[row0 * 64 + col] = h;       g_dr_lo[row0 * 64 + col] = l;
                    split1(v0.y, h, l); g_dr_hi[row0 * 64 + col + 1] = h;   g_dr_lo[row0 * 64 + col + 1] = l;
                    split1(v1.x, h, l); g_dr_hi[(row0 + 8) * 64 + col] = h; g_dr_lo[(row0 + 8) * 64 + col] = l;
                    split1(v1.y, h, l); g_dr_hi[(row0 + 8) * 64 + col + 1] = h; g_dr_lo[(row0 + 8) * 64 + col + 1] = l;
                }
            }
        }
    }
}

// ---------------- RMSNorm -> u bf16 planes ----------------
__global__ void rmsnorm_kernel(const float* __restrict__ in,
                               const float* __restrict__ scale) {
    int l = blockIdx.x;
    int t = threadIdx.x;
    const float* row = in + (size_t)l * DM;
    float s = 0.f;
    for (int i = t; i < DM; i += 256) { float v = row[i]; s += v * v; }
    __shared__ float red[256];
    red[t] = s; __syncthreads();
    for (int o = 128; o > 0; o >>= 1) {
        if (t < o) red[t] += red[t + o];
        __syncthreads();
    }
    float inv = rsqrtf(red[0] * (1.f / DM) + 1e-6f);
    for (int i = t; i < DM; i += 256) {
        float v = row[i] * inv * scale[i];
        __nv_bfloat16 h, lo;
        split1(v, h, lo);
        g_u_hi[(size_t)l * DM + i] = h;
        g_u_lo[(size_t)l * DM + i] = lo;
    }
}

// ---------------- depthwise conv along d_inner + SiLU ----------------
__global__ void conv_silu_kernel(const float* __restrict__ cw,
                                 const float* __restrict__ cb) {
    int l = blockIdx.x;
    int t = threadIdx.x;
    __shared__ float xs[DI];
    const float4* src = (const float4*)(g_xres + (size_t)l * 2 * DI);
    float4* dst4 = (float4*)xs;
    for (int i = t; i < DI / 4; i += 256) dst4[i] = src[i];
    __syncthreads();
    float w0 = cw[l], w1 = cw[DI + l], w2 = cw[2 * DI + l], w3 = cw[3 * DI + l];
    float b = cb[l];
    for (int d = t; d < DI; d += 256) {
        float xm1 = (d > 0) ? xs[d - 1] : 0.f;
        float x0  = xs[d];
        float xp1 = (d < DI - 1) ? xs[d + 1] : 0.f;
        float xp2 = (d < DI - 2) ? xs[d + 2] : 0.f;
        float v = b + w0 * xm1 + w1 * x0 + w2 * xp1 + w3 * xp2;
        g_xconv[(size_t)l * DI + d] = v * (1.f / (1.f + __expf(-v)));
    }
}

// ---------------- selective scan -> y bf16 planes ----------------
__global__ void __launch_bounds__(256) scan_kernel(const float* __restrict__ A_log,
                                                   const float* __restrict__ Dp) {
    __shared__ float sdelta[16][16], sx[16][16], sB[16][16], sC[16][16], sres[16][16];
    int t = threadIdx.x;
    int g = t >> 4;
    int n = t & 15;
    int d0 = blockIdx.x * 16;
    int d  = d0 + g;

    float a  = -expf(A_log[(size_t)d * DS + n]);
    float Dd = Dp[d];
    float h  = 0.f;

    float pd = g_delta[(size_t)g * DI + d0 + n];
    float px = g_xconv[(size_t)g * DI + d0 + n];
    float pr = g_xres[(size_t)g * 2 * DI + DI + d0 + n];
    float pB = g_xdbl[(size_t)g * 96 + 64 + n];
    float pC = g_xdbl[(size_t)g * 96 + 80 + n];

    for (int l0 = 0; l0 < LSEQ; l0 += 16) {
        sdelta[g][n] = pd; sx[g][n] = px; sres[g][n] = pr; sB[g][n] = pB; sC[g][n] = pC;
        __syncthreads();
        if (l0 + 16 < LSEQ) {
            int l = l0 + 16 + g;
            pd = g_delta[(size_t)l * DI + d0 + n];
            px = g_xconv[(size_t)l * DI + d0 + n];
            pr = g_xres[(size_t)l * 2 * DI + DI + d0 + n];
            pB = g_xdbl[(size_t)l * 96 + 64 + n];
            pC = g_xdbl[(size_t)l * 96 + 80 + n];
        }
        #pragma unroll
        for (int i = 0; i < 16; ++i) {
            float dlt = sdelta[i][g];
            float xv  = sx[i][g];
            float dA  = __expf(dlt * a);
            h = fmaf(dA, h, dlt * sB[i][n] * xv);
            float yp = h * sC[i][n];
            yp += __shfl_xor_sync(0xffffffffu, yp, 8, 16);
            yp += __shfl_xor_sync(0xffffffffu, yp, 4, 16);
            yp += __shfl_xor_sync(0xffffffffu, yp, 2, 16);
            yp += __shfl_xor_sync(0xffffffffu, yp, 1, 16);
            if (n == 0) {
                float r = sres[i][g];
                float val = (yp + xv * Dd) * (r / (1.f + __expf(-r)));
                __nv_bfloat16 hb, lb;
                split1(val, hb, lb);
                size_t idx = (size_t)(l0 + i) * DI + d;
                g_y_hi[idx] = hb;
                g_y_lo[idx] = lb;
            }
        }
        __syncthreads();
    }
}

// ---------------- launch ----------------
extern "C" void kernel_launch(void* const* d_in, const int* in_sizes, int n_in,
                              void* d_out, int out_size) {
    const float* inputs     = (const float*)d_in[0];
    const float* norm_scale = (const float*)d_in[1];
    const float* in_proj_w  = (const float*)d_in[2];
    const float* conv_w     = (const float*)d_in[3];
    const float* conv_b     = (const float*)d_in[4];
    const float* x_proj_w   = (const float*)d_in[5];
    const float* dt_proj_w  = (const float*)d_in[6];
    const float* dt_proj_b  = (const float*)d_in[7];
    const float* out_proj_w = (const float*)d_in[8];
    const float* A_log      = (const float*)d_in[9];
    const float* Dvec       = (const float*)d_in[10];
    float* out = (float*)d_out;

    void *p_xres, *p_xdbl, *p_delta;
    void *p_uh, *p_ul, *p_drh, *p_drl, *p_yh, *p_yl;
    void *p_w1h, *p_w1l, *p_w2h, *p_w2l, *p_w3h, *p_w3l, *p_w4h, *p_w4l;
    cudaGetSymbolAddress(&p_xres, g_xres);
    cudaGetSymbolAddress(&p_xdbl, g_xdbl);
    cudaGetSymbolAddress(&p_delta, g_delta);
    cudaGetSymbolAddress(&p_uh, g_u_hi);   cudaGetSymbolAddress(&p_ul, g_u_lo);
    cudaGetSymbolAddress(&p_drh, g_dr_hi); cudaGetSymbolAddress(&p_drl, g_dr_lo);
    cudaGetSymbolAddress(&p_yh, g_y_hi);   cudaGetSymbolAddress(&p_yl, g_y_lo);
    cudaGetSymbolAddress(&p_w1h, g_w1h);   cudaGetSymbolAddress(&p_w1l, g_w1l);
    cudaGetSymbolAddress(&p_w2h, g_w2h);   cudaGetSymbolAddress(&p_w2l, g_w2l);
    cudaGetSymbolAddress(&p_w3h, g_w3h);   cudaGetSymbolAddress(&p_w3l, g_w3l);
    cudaGetSymbolAddress(&p_w4h, g_w4h);   cudaGetSymbolAddress(&p_w4l, g_w4l);

    const int SMEM = 3 * 37888;  // 113664
    cudaFuncSetAttribute(hgemm, cudaFuncAttributeMaxDynamicSharedMemorySize, SMEM);

    // 0) weight conversions
    convert_split<<<(DM * 2 * DI / 4 + 255) / 256, 256>>>(in_proj_w,  (__nv_bfloat16*)p_w1h, (__nv_bfloat16*)p_w1l, DM * 2 * DI / 4);
    convert_split<<<(DM * 96 / 4 + 255) / 256, 256>>>(x_proj_w,   (__nv_bfloat16*)p_w2h, (__nv_bfloat16*)p_w2l, DM * 96 / 4);
    convert_split<<<(64 * DI / 4 + 255) / 256, 256>>>(dt_proj_w,  (__nv_bfloat16*)p_w3h, (__nv_bfloat16*)p_w3l, 64 * DI / 4);
    convert_split<<<(DI * DM / 4 + 255) / 256, 256>>>(out_proj_w, (__nv_bfloat16*)p_w4h, (__nv_bfloat16*)p_w4l, DI * DM / 4);

    // 1) RMSNorm -> u planes
    rmsnorm_kernel<<<LSEQ, 256>>>(inputs, norm_scale);

    // 2) fused G1+G2: blocks 0..31 -> in_proj (xres), block 32 -> x_proj (xdbl + dr planes)
    hgemm<<<dim3(33, 16), 256, SMEM>>>(
        (const __nv_bfloat16*)p_uh, (const __nv_bfloat16*)p_ul, DM,
        (const __nv_bfloat16*)p_w1h, (const __nv_bfloat16*)p_w1l, 2 * DI,
        (float*)p_xres, 2 * DI, nullptr, 0,
        DM, 2 * DI, 0, 32,
        (const __nv_bfloat16*)p_w2h, (const __nv_bfloat16*)p_w2l, 96,
        (float*)p_xdbl, 96, 96, 3);

    // 3) conv + silu
    conv_silu_kernel<<<LSEQ, 256>>>(conv_w, conv_b);

    // 4) G3: dr @ dt_proj_w + bias, softplus -> delta
    hgemm<<<dim3(16, 16), 256, SMEM>>>(
        (const __nv_bfloat16*)p_drh, (const __nv_bfloat16*)p_drl, 64,
        (const __nv_bfloat16*)p_w3h, (const __nv_bfloat16*)p_w3l, DI,
        (float*)p_delta, DI, dt_proj_b, 0,
        64, DI, 2, 1 << 30,
        nullptr, nullptr, 0, nullptr, 0, 0, 0);

    // 5) scan -> y planes
    scan_kernel<<<DI / 16, 256>>>(A_log, Dvec);

    // 6) G4: y @ out_proj_w + inputs -> out
    hgemm<<<dim3(8, 16), 256, SMEM>>>(
        (const __nv_bfloat16*)p_yh, (const __nv_bfloat16*)p_yl, DI,
        (const __nv_bfloat16*)p_w4h, (const __nv_bfloat16*)p_w4l, DM,
        out, DM, inputs, DM,
        DI, DM, 1, 1 << 30,
        nullptr, nullptr, 0, nullptr, 0, 0, 0);
}

// round 6
// speedup vs baseline: 2.5071x; 1.5070x over previous
#include <cuda_runtime.h>
#include <cuda_bf16.h>
#include <cstdint>

#define LSEQ 2048
#define DM   1024
#define DI   2048
#define DS   16

// ---------------- scratch ----------------
__device__ float g_xres[LSEQ * 2 * DI];           // G1 out (x | res), fp32
__device__ float g_xconv[LSEQ * DI];              // conv+silu, fp32
__device__ float g_xdbl[LSEQ * 96];               // x_proj out, fp32 (B,C for scan)
__device__ float g_delta[LSEQ * DI];              // softplus delta, fp32
__device__ __nv_bfloat16 g_u_hi[LSEQ * DM],  g_u_lo[LSEQ * DM];
__device__ __nv_bfloat16 g_dr_hi[LSEQ * 64], g_dr_lo[LSEQ * 64];
__device__ __nv_bfloat16 g_y_hi[LSEQ * DI],  g_y_lo[LSEQ * DI];
// weight planes
__device__ __nv_bfloat16 g_w1h[DM * 2 * DI], g_w1l[DM * 2 * DI];
__device__ __nv_bfloat16 g_w2h[DM * 96],     g_w2l[DM * 96];
__device__ __nv_bfloat16 g_w3h[64 * DI],     g_w3l[64 * DI];
__device__ __nv_bfloat16 g_w4h[DI * DM],     g_w4l[DI * DM];

__device__ __forceinline__ float softplus_f(float x) {
    return fmaxf(x, 0.f) + log1pf(__expf(-fabsf(x)));
}
__device__ __forceinline__ uint32_t smem_to_u32(const void* p) {
    uint32_t a;
    asm("{ .reg .u64 t; cvta.to.shared.u64 t, %1; cvt.u32.u64 %0, t; }" : "=r"(a) : "l"(p));
    return a;
}
__device__ __forceinline__ void ldsm4(uint32_t* r, uint32_t addr) {
    asm volatile("ldmatrix.sync.aligned.m8n8.x4.shared.b16 {%0,%1,%2,%3}, [%4];"
                 : "=r"(r[0]), "=r"(r[1]), "=r"(r[2]), "=r"(r[3]) : "r"(addr));
}
__device__ __forceinline__ void ldsm4t(uint32_t* r, uint32_t addr) {
    asm volatile("ldmatrix.sync.aligned.m8n8.x4.trans.shared.b16 {%0,%1,%2,%3}, [%4];"
                 : "=r"(r[0]), "=r"(r[1]), "=r"(r[2]), "=r"(r[3]) : "r"(addr));
}
__device__ __forceinline__ void mma_bf16(float* c, const uint32_t* a, const uint32_t* b) {
    asm volatile("mma.sync.aligned.m16n8k16.row.col.f32.bf16.bf16.f32 "
                 "{%0,%1,%2,%3}, {%4,%5,%6,%7}, {%8,%9}, {%0,%1,%2,%3};"
                 : "+f"(c[0]), "+f"(c[1]), "+f"(c[2]), "+f"(c[3])
                 : "r"(a[0]), "r"(a[1]), "r"(a[2]), "r"(a[3]), "r"(b[0]), "r"(b[1]));
}
__device__ __forceinline__ void cp16(uint32_t dst, const void* src, int sz) {
    asm volatile("cp.async.cg.shared.global [%0], [%1], 16, %2;" :: "r"(dst), "l"(src), "r"(sz));
}
#define CP_COMMIT() asm volatile("cp.async.commit_group;" ::: "memory")
#define CP_WAIT1()  asm volatile("cp.async.wait_group 1;" ::: "memory")

__device__ __forceinline__ void split1(float x, __nv_bfloat16& h, __nv_bfloat16& l) {
    h = __float2bfloat16_rn(x);
    l = __float2bfloat16_rn(x - __bfloat162float(h));
}

// ---------------- fused fp32 -> bf16 hi/lo plane converter (all 4 weights) ----------------
__global__ void convert_all(const float* __restrict__ w1, __nv_bfloat16* h1, __nv_bfloat16* l1,
                            const float* __restrict__ w2, __nv_bfloat16* h2, __nv_bfloat16* l2,
                            const float* __restrict__ w3, __nv_bfloat16* h3, __nv_bfloat16* l3,
                            const float* __restrict__ w4, __nv_bfloat16* h4, __nv_bfloat16* l4) {
    constexpr int N1 = DM * 2 * DI / 4;   // 1048576
    constexpr int N2 = DM * 96 / 4;       // 24576
    constexpr int N3 = 64 * DI / 4;       // 32768
    constexpr int N4 = DI * DM / 4;       // 524288
    int i = blockIdx.x * blockDim.x + threadIdx.x;
    const float* src;
    __nv_bfloat16 *hi, *lo;
    if (i < N1)                      { src = w1; hi = h1; lo = l1; }
    else if ((i -= N1) < N2)         { src = w2; hi = h2; lo = l2; }
    else if ((i -= N2) < N3)         { src = w3; hi = h3; lo = l3; }
    else if ((i -= N3) < N4)         { src = w4; hi = h4; lo = l4; }
    else return;
    float4 v = ((const float4*)src)[i];
    __nv_bfloat16 h[4], l[4];
    split1(v.x, h[0], l[0]); split1(v.y, h[1], l[1]);
    split1(v.z, h[2], l[2]); split1(v.w, h[3], l[3]);
    ((uint2*)hi)[i] = make_uint2(
        (uint32_t)__bfloat16_as_ushort(h[0]) | ((uint32_t)__bfloat16_as_ushort(h[1]) << 16),
        (uint32_t)__bfloat16_as_ushort(h[2]) | ((uint32_t)__bfloat16_as_ushort(h[3]) << 16));
    ((uint2*)lo)[i] = make_uint2(
        (uint32_t)__bfloat16_as_ushort(l[0]) | ((uint32_t)__bfloat16_as_ushort(l[1]) << 16),
        (uint32_t)__bfloat16_as_ushort(l[2]) | ((uint32_t)__bfloat16_as_ushort(l[3]) << 16));
}

// ---------------- split-bf16 HMMA GEMM, cp.async 3-stage, 1 sync/k-tile ----------------
__global__ void __launch_bounds__(256, 1) hgemm(
    const __nv_bfloat16* __restrict__ Ah, const __nv_bfloat16* __restrict__ Al, int lda,
    const __nv_bfloat16* Bh, const __nv_bfloat16* Bl, int ldb,
    float* C, int ldc, const float* __restrict__ extra, int lde,
    int K, int n_real, int epi, int nsplit,
    const __nv_bfloat16* B2h, const __nv_bfloat16* B2l, int ldb2,
    float* C2, int ldc2, int n2, int epi2)
{
    extern __shared__ char sm[];
    constexpr int APL = 10240;            // A plane bytes (128*80)
    constexpr int BPL = 8704;             // B plane bytes (32*272)
    constexpr int STG = 2 * APL + 2 * BPL;  // 37888 per stage

    int tid = threadIdx.x, wid = tid >> 5, lane = tid & 31;
    int bxi = blockIdx.x;
    int bx;
    if (bxi >= nsplit) {
        Bh = B2h; Bl = B2l; ldb = ldb2; C = C2; ldc = ldc2;
        n_real = n2; epi = epi2; bx = (bxi - nsplit) * 128;
    } else {
        bx = bxi * 128;
    }
    int by = blockIdx.y * 128;
    int wm = (wid >> 2) * 64, wn = (wid & 3) * 32;
    uint32_t smb = smem_to_u32(sm);

    float acc[4][4][4];
    #pragma unroll
    for (int i = 0; i < 4; ++i)
        #pragma unroll
        for (int j = 0; j < 4; ++j)
            #pragma unroll
            for (int r = 0; r < 4; ++r) acc[i][j][r] = 0.f;

    int T = K >> 5;

    auto load_stage = [&](int s) {
        uint32_t base = smb + (s % 3) * STG;
        int kb = s << 5;
        #pragma unroll
        for (int i = 0; i < 4; ++i) {
            int pid = i * 256 + tid;
            int pl = pid >> 9, rem = pid & 511;
            int row = rem >> 2, ch = rem & 3;
            const __nv_bfloat16* src = (pl ? Al : Ah) + (size_t)(by + row) * lda + kb + ch * 8;
            cp16(base + pl * APL + row * 80 + ch * 16, src, 16);
        }
        #pragma unroll
        for (int i = 0; i < 4; ++i) {
            int pid = i * 256 + tid;
            int pl = pid >> 9, rem = pid & 511;
            int k = rem >> 4, ch = rem & 15;
            int col = bx + ch * 8;
            bool v = col < n_real;
            const __nv_bfloat16* src = v ? ((pl ? Bl : Bh) + (size_t)(kb + k) * ldb + col)
                                         : Bh;
            cp16(base + 2 * APL + pl * BPL + k * 272 + ch * 16, src, v ? 16 : 0);
        }
    };

    load_stage(0); CP_COMMIT();
    if (T > 1) { load_stage(1); }
    CP_COMMIT();

    for (int s = 0; s < T; ++s) {
        CP_WAIT1();
        __syncthreads();   // single barrier per k-tile: orders compute(s-1) before load(s+2)
        if (s + 2 < T) load_stage(s + 2);
        CP_COMMIT();

        uint32_t bA  = smb + (s % 3) * STG;
        uint32_t bAl = bA + APL;
        uint32_t bBh = bA + 2 * APL;
        uint32_t bBl = bBh + BPL;
        #pragma unroll
        for (int kk = 0; kk < 2; ++kk) {
            int k0 = kk * 16;
            uint32_t ah[4][4], al[4][4], bh[2][4], bl[2][4];
            int arow = wm + (lane & 15);
            int acol = k0 + ((lane >> 4) << 3);
            #pragma unroll
            for (int mt = 0; mt < 4; ++mt) {
                uint32_t off = (uint32_t)((arow + mt * 16) * 80 + acol * 2);
                ldsm4(ah[mt], bA + off);
                ldsm4(al[mt], bAl + off);
            }
            int bk = k0 + (lane & 15);
            #pragma unroll
            for (int ns = 0; ns < 2; ++ns) {
                int bn = wn + ns * 16 + ((lane >> 4) << 3);
                uint32_t off = (uint32_t)(bk * 272 + bn * 2);
                ldsm4t(bh[ns], bBh + off);
                ldsm4t(bl[ns], bBl + off);
            }
            #pragma unroll
            for (int mt = 0; mt < 4; ++mt)
                #pragma unroll
                for (int nt = 0; nt < 4; ++nt) {
                    const uint32_t* bph = &bh[nt >> 1][(nt & 1) * 2];
                    const uint32_t* bpl = &bl[nt >> 1][(nt & 1) * 2];
                    mma_bf16(acc[mt][nt], ah[mt], bph);
                    mma_bf16(acc[mt][nt], ah[mt], bpl);
                    mma_bf16(acc[mt][nt], al[mt], bph);
                }
        }
    }

    // ---- epilogue ----
    #pragma unroll
    for (int mt = 0; mt < 4; ++mt) {
        #pragma unroll
        for (int nt = 0; nt < 4; ++nt) {
            int row0 = by + wm + mt * 16 + (lane >> 2);
            int col  = bx + wn + nt * 8 + (lane & 3) * 2;
            if (col < n_real) {
                float* a = acc[mt][nt];
                float2 v0 = make_float2(a[0], a[1]);
                float2 v1 = make_float2(a[2], a[3]);
                if (epi == 1) {
                    float2 e0 = *(const float2*)(extra + (size_t)row0 * lde + col);
                    float2 e1 = *(const float2*)(extra + (size_t)(row0 + 8) * lde + col);
                    v0.x += e0.x; v0.y += e0.y;
                    v1.x += e1.x; v1.y += e1.y;
                } else if (epi == 2) {
                    float b0 = extra[col], b1 = extra[col + 1];
                    v0.x = softplus_f(v0.x + b0);
                    v0.y = softplus_f(v0.y + b1);
                    v1.x = softplus_f(v1.x + b0);
                    v1.y = softplus_f(v1.y + b1);
                }
                *(float2*)(C + (size_t)row0 * ldc + col)       = v0;
                *(float2*)(C + (size_t)(row0 + 8) * ldc + col) = v1;
                if (epi == 3 && col < 64) {
                    __nv_bfloat16 h, l;
                    split1(v0.x, h, l); g_dr_hi[row0 * 64 + col] = h;       g_dr_lo[row0 * 64 + col] = l;
                    split1(v0.y, h, l); g_dr_hi[row0 * 64 + col + 1] = h;   g_dr_lo[row0 * 64 + col + 1] = l;
                    split1(v1.x, h, l); g_dr_hi[(row0 + 8) * 64 + col] = h; g_dr_lo[(row0 + 8) * 64 + col] = l;
                    split1(v1.y, h, l); g_dr_hi[(row0 + 8) * 64 + col + 1] = h; g_dr_lo[(row0 + 8) * 64 + col + 1] = l;
                }
            }
        }
    }
}

// ---------------- RMSNorm -> u bf16 planes ----------------
__global__ void rmsnorm_kernel(const float* __restrict__ in,
                               const float* __restrict__ scale) {
    int l = blockIdx.x;
    int t = threadIdx.x;
    const float* row = in + (size_t)l * DM;
    float s = 0.f;
    for (int i = t; i < DM; i += 256) { float v = row[i]; s += v * v; }
    __shared__ float red[256];
    red[t] = s; __syncthreads();
    for (int o = 128; o > 0; o >>= 1) {
        if (t < o) red[t] += red[t + o];
        __syncthreads();
    }
    float inv = rsqrtf(red[0] * (1.f / DM) + 1e-6f);
    for (int i = t; i < DM; i += 256) {
        float v = row[i] * inv * scale[i];
        __nv_bfloat16 h, lo;
        split1(v, h, lo);
        g_u_hi[(size_t)l * DM + i] = h;
        g_u_lo[(size_t)l * DM + i] = lo;
    }
}

// ---------------- depthwise conv along d_inner + SiLU ----------------
__global__ void conv_silu_kernel(const float* __restrict__ cw,
                                 const float* __restrict__ cb) {
    int l = blockIdx.x;
    int t = threadIdx.x;
    __shared__ float xs[DI];
    const float4* src = (const float4*)(g_xres + (size_t)l * 2 * DI);
    float4* dst4 = (float4*)xs;
    for (int i = t; i < DI / 4; i += 256) dst4[i] = src[i];
    __syncthreads();
    float w0 = cw[l], w1 = cw[DI + l], w2 = cw[2 * DI + l], w3 = cw[3 * DI + l];
    float b = cb[l];
    for (int d = t; d < DI; d += 256) {
        float xm1 = (d > 0) ? xs[d - 1] : 0.f;
        float x0  = xs[d];
        float xp1 = (d < DI - 1) ? xs[d + 1] : 0.f;
        float xp2 = (d < DI - 2) ? xs[d + 2] : 0.f;
        float v = b + w0 * xm1 + w1 * x0 + w2 * xp1 + w3 * xp2;
        g_xconv[(size_t)l * DI + d] = v * (1.f / (1.f + __expf(-v)));
    }
}

// ---------------- selective scan, phase-split (no shfl chain) ----------------
// phase 1: thread (g=channel, n=state) does 16 serial h updates, stores h*C to smem
// phase 2: thread (i=step, g2=channel) sums 16 states, applies +x*D and *silu(res)
__global__ void __launch_bounds__(256) scan_kernel(const float* __restrict__ A_log,
                                                   const float* __restrict__ Dp) {
    __shared__ float sdelta[16][16], sx[16][16], sB[16][16], sC[16][16], sres[16][16];
    __shared__ float sp[16 * 272 + 16];   // sp[i*272 + g*17 + n]
    int t = threadIdx.x;
    int g = t >> 4;
    int n = t & 15;
    int d0 = blockIdx.x * 16;
    int d  = d0 + g;

    float a  = -expf(A_log[(size_t)d * DS + n]);
    float h  = 0.f;
    // phase-2 identity
    int i2 = t >> 4;          // timestep in chunk
    int g2 = t & 15;          // channel
    float Dd2 = Dp[d0 + g2];

    float pd = g_delta[(size_t)g * DI + d0 + n];
    float px = g_xconv[(size_t)g * DI + d0 + n];
    float pr = g_xres[(size_t)g * 2 * DI + DI + d0 + n];
    float pB = g_xdbl[(size_t)g * 96 + 64 + n];
    float pC = g_xdbl[(size_t)g * 96 + 80 + n];

    for (int l0 = 0; l0 < LSEQ; l0 += 16) {
        sdelta[g][n] = pd; sx[g][n] = px; sres[g][n] = pr; sB[g][n] = pB; sC[g][n] = pC;
        __syncthreads();
        if (l0 + 16 < LSEQ) {
            int l = l0 + 16 + g;
            pd = g_delta[(size_t)l * DI + d0 + n];
            px = g_xconv[(size_t)l * DI + d0 + n];
            pr = g_xres[(size_t)l * 2 * DI + DI + d0 + n];
            pB = g_xdbl[(size_t)l * 96 + 64 + n];
            pC = g_xdbl[(size_t)l * 96 + 80 + n];
        }
        // phase 1: serial scan over 16 steps (exp off critical path)
        #pragma unroll
        for (int i = 0; i < 16; ++i) {
            float dlt = sdelta[i][g];
            float dA  = __expf(dlt * a);
            h = fmaf(dA, h, dlt * sB[i][n] * sx[i][g]);
            sp[i * 272 + g * 17 + n] = h * sC[i][n];
        }
        __syncthreads();
        // phase 2: parallel reduction over n
        {
            const float* base = &sp[i2 * 272 + g2 * 17];
            float s0 = base[0] + base[1], s1 = base[2] + base[3];
            float s2 = base[4] + base[5], s3 = base[6] + base[7];
            float s4 = base[8] + base[9], s5 = base[10] + base[11];
            float s6 = base[12] + base[13], s7 = base[14] + base[15];
            float sum = ((s0 + s1) + (s2 + s3)) + ((s4 + s5) + (s6 + s7));
            float xv = sx[i2][g2];
            float r  = sres[i2][g2];
            float val = (sum + xv * Dd2) * (r / (1.f + __expf(-r)));
            __nv_bfloat16 hb, lb;
            split1(val, hb, lb);
            size_t idx = (size_t)(l0 + i2) * DI + d0 + g2;
            g_y_hi[idx] = hb;
            g_y_lo[idx] = lb;
        }
        __syncthreads();
    }
}

// ---------------- launch ----------------
extern "C" void kernel_launch(void* const* d_in, const int* in_sizes, int n_in,
                              void* d_out, int out_size) {
    const float* inputs     = (const float*)d_in[0];
    const float* norm_scale = (const float*)d_in[1];
    const float* in_proj_w  = (const float*)d_in[2];
    const float* conv_w     = (const float*)d_in[3];
    const float* conv_b     = (const float*)d_in[4];
    const float* x_proj_w   = (const float*)d_in[5];
    const float* dt_proj_w  = (const float*)d_in[6];
    const float* dt_proj_b  = (const float*)d_in[7];
    const float* out_proj_w = (const float*)d_in[8];
    const float* A_log      = (const float*)d_in[9];
    const float* Dvec       = (const float*)d_in[10];
    float* out = (float*)d_out;

    void *p_xres, *p_xdbl, *p_delta;
    void *p_uh, *p_ul, *p_drh, *p_drl, *p_yh, *p_yl;
    void *p_w1h, *p_w1l, *p_w2h, *p_w2l, *p_w3h, *p_w3l, *p_w4h, *p_w4l;
    cudaGetSymbolAddress(&p_xres, g_xres);
    cudaGetSymbolAddress(&p_xdbl, g_xdbl);
    cudaGetSymbolAddress(&p_delta, g_delta);
    cudaGetSymbolAddress(&p_uh, g_u_hi);   cudaGetSymbolAddress(&p_ul, g_u_lo);
    cudaGetSymbolAddress(&p_drh, g_dr_hi); cudaGetSymbolAddress(&p_drl, g_dr_lo);
    cudaGetSymbolAddress(&p_yh, g_y_hi);   cudaGetSymbolAddress(&p_yl, g_y_lo);
    cudaGetSymbolAddress(&p_w1h, g_w1h);   cudaGetSymbolAddress(&p_w1l, g_w1l);
    cudaGetSymbolAddress(&p_w2h, g_w2h);   cudaGetSymbolAddress(&p_w2l, g_w2l);
    cudaGetSymbolAddress(&p_w3h, g_w3h);   cudaGetSymbolAddress(&p_w3l, g_w3l);
    cudaGetSymbolAddress(&p_w4h, g_w4h);   cudaGetSymbolAddress(&p_w4l, g_w4l);

    const int SMEM = 3 * 37888;  // 113664
    cudaFuncSetAttribute(hgemm, cudaFuncAttributeMaxDynamicSharedMemorySize, SMEM);

    // 0) all weight conversions in one launch
    {
        const int NTOT = DM * 2 * DI / 4 + DM * 96 / 4 + 64 * DI / 4 + DI * DM / 4;
        convert_all<<<(NTOT + 255) / 256, 256>>>(
            in_proj_w,  (__nv_bfloat16*)p_w1h, (__nv_bfloat16*)p_w1l,
            x_proj_w,   (__nv_bfloat16*)p_w2h, (__nv_bfloat16*)p_w2l,
            dt_proj_w,  (__nv_bfloat16*)p_w3h, (__nv_bfloat16*)p_w3l,
            out_proj_w, (__nv_bfloat16*)p_w4h, (__nv_bfloat16*)p_w4l);
    }

    // 1) RMSNorm -> u planes
    rmsnorm_kernel<<<LSEQ, 256>>>(inputs, norm_scale);

    // 2) fused G1+G2: blocks 0..31 -> in_proj (xres), block 32 -> x_proj (xdbl + dr planes)
    hgemm<<<dim3(33, 16), 256, SMEM>>>(
        (const __nv_bfloat16*)p_uh, (const __nv_bfloat16*)p_ul, DM,
        (const __nv_bfloat16*)p_w1h, (const __nv_bfloat16*)p_w1l, 2 * DI,
        (float*)p_xres, 2 * DI, nullptr, 0,
        DM, 2 * DI, 0, 32,
        (const __nv_bfloat16*)p_w2h, (const __nv_bfloat16*)p_w2l, 96,
        (float*)p_xdbl, 96, 96, 3);

    // 3) conv + silu
    conv_silu_kernel<<<LSEQ, 256>>>(conv_w, conv_b);

    // 4) G3: dr @ dt_proj_w + bias, softplus -> delta
    hgemm<<<dim3(16, 16), 256, SMEM>>>(
        (const __nv_bfloat16*)p_drh, (const __nv_bfloat16*)p_drl, 64,
        (const __nv_bfloat16*)p_w3h, (const __nv_bfloat16*)p_w3l, DI,
        (float*)p_delta, DI, dt_proj_b, 0,
        64, DI, 2, 1 << 30,
        nullptr, nullptr, 0, nullptr, 0, 0, 0);

    // 5) scan -> y planes
    scan_kernel<<<DI / 16, 256>>>(A_log, Dvec);

    // 6) G4: y @ out_proj_w + inputs -> out
    hgemm<<<dim3(8, 16), 256, SMEM>>>(
        (const __nv_bfloat16*)p_yh, (const __nv_bfloat16*)p_yl, DI,
        (const __nv_bfloat16*)p_w4h, (const __nv_bfloat16*)p_w4l, DM,
        out, DM, inputs, DM,
        DI, DM, 1, 1 << 30,
        nullptr, nullptr, 0, nullptr, 0, 0, 0);
}

// round 8
// speedup vs baseline: 3.1146x; 1.2423x over previous
#include <cuda_runtime.h>
#include <cuda_bf16.h>
#include <cstdint>

#define LSEQ 2048
#define DM   1024
#define DI   2048
#define DS   16

// ---------------- scratch ----------------
__device__ float g_xres[LSEQ * 2 * DI];   // G1 out (x | res), fp32
__device__ float g_xconv[LSEQ * DI];      // conv+silu, fp32
__device__ float g_xdbl[LSEQ * 96];       // x_proj out, fp32 (B,C for scan)
__device__ float g_delta[LSEQ * DI];      // softplus delta, fp32
__device__ float g_u_t[LSEQ * DM];        // rmsnorm out, tf32-rounded
__device__ float g_dr_t[LSEQ * 64];       // delta_r, tf32-rounded
__device__ float g_y_t[LSEQ * DI];        // scan out, tf32-rounded
// tf32-rounded weights
__device__ float g_w1t[DM * 2 * DI];
__device__ float g_w2t[DM * 96];
__device__ float g_w3t[64 * DI];
__device__ float g_w4t[DI * DM];

__device__ __forceinline__ float softplus_f(float x) {
    return fmaxf(x, 0.f) + log1pf(__expf(-fabsf(x)));
}
__device__ __forceinline__ float tf32r(float x) {
    uint32_t r;
    asm("cvt.rna.tf32.f32 %0, %1;" : "=r"(r) : "f"(x));
    return __uint_as_float(r);
}
__device__ __forceinline__ uint32_t smem_to_u32(const void* p) {
    uint32_t a;
    asm("{ .reg .u64 t; cvta.to.shared.u64 t, %1; cvt.u32.u64 %0, t; }" : "=r"(a) : "l"(p));
    return a;
}
__device__ __forceinline__ void ldsm4(uint32_t* r, uint32_t addr) {
    asm volatile("ldmatrix.sync.aligned.m8n8.x4.shared.b16 {%0,%1,%2,%3}, [%4];"
                 : "=r"(r[0]), "=r"(r[1]), "=r"(r[2]), "=r"(r[3]) : "r"(addr));
}
__device__ __forceinline__ void mma_tf32(float* c, const uint32_t* a, uint32_t b0, uint32_t b1) {
    asm volatile("mma.sync.aligned.m16n8k8.row.col.f32.tf32.tf32.f32 "
                 "{%0,%1,%2,%3}, {%4,%5,%6,%7}, {%8,%9}, {%0,%1,%2,%3};"
                 : "+f"(c[0]), "+f"(c[1]), "+f"(c[2]), "+f"(c[3])
                 : "r"(a[0]), "r"(a[1]), "r"(a[2]), "r"(a[3]), "r"(b0), "r"(b1));
}
__device__ __forceinline__ void cp16(uint32_t dst, const void* src, int sz) {
    asm volatile("cp.async.cg.shared.global [%0], [%1], 16, %2;" :: "r"(dst), "l"(src), "r"(sz));
}
#define CP_COMMIT() asm volatile("cp.async.commit_group;" ::: "memory")
#define CP_WAIT1()  asm volatile("cp.async.wait_group 1;" ::: "memory")

// ---------------- fused weight converter: fp32 -> tf32-rounded fp32 ----------------
__global__ void convert_all(const float* __restrict__ w1, float* d1,
                            const float* __restrict__ w2, float* d2,
                            const float* __restrict__ w3, float* d3,
                            const float* __restrict__ w4, float* d4) {
    constexpr int N1 = DM * 2 * DI / 4;
    constexpr int N2 = DM * 96 / 4;
    constexpr int N3 = 64 * DI / 4;
    constexpr int N4 = DI * DM / 4;
    int i = blockIdx.x * blockDim.x + threadIdx.x;
    const float* src;
    float* dst;
    if (i < N1)              { src = w1; dst = d1; }
    else if ((i -= N1) < N2) { src = w2; dst = d2; }
    else if ((i -= N2) < N3) { src = w3; dst = d3; }
    else if ((i -= N3) < N4) { src = w4; dst = d4; }
    else return;
    float4 v = ((const float4*)src)[i];
    v.x = tf32r(v.x); v.y = tf32r(v.y); v.z = tf32r(v.z); v.w = tf32r(v.w);
    ((float4*)dst)[i] = v;
}

// ---------------- tf32 HMMA GEMM, cp.async 3-stage, occupancy 2 ----------------
// tile 128x128xBK32; 8 warps (2x4), warp 64x32, per warp 4x4 m16n8 tiles.
// A smem [128][36] f32 (144B rows), B smem [32][132] f32 (528B rows).
// epi: 0 plain, 1 +extra[r*lde+c], 2 softplus(acc+extra[c]), 3 plain + dr_t (c<64)
__global__ void __launch_bounds__(256, 2) hgemm(
    const float* __restrict__ A, int lda,
    const float* Bm, int ldb,
    float* C, int ldc, const float* __restrict__ extra, int lde,
    int K, int n_real, int epi, int nsplit,
    const float* B2, int ldb2, float* C2, int ldc2, int n2, int epi2)
{
    extern __shared__ char sm[];
    constexpr int ASTRIDE = 36;                 // words
    constexpr int BSTRIDE = 132;                // words
    constexpr int ABYT = 128 * ASTRIDE * 4;     // 18432
    constexpr int BBYT = 32 * BSTRIDE * 4;      // 16896
    constexpr int STG  = ABYT + BBYT;           // 35328

    int tid = threadIdx.x, wid = tid >> 5, lane = tid & 31;
    int bxi = blockIdx.x;
    int bx;
    if (bxi >= nsplit) {
        Bm = B2; ldb = ldb2; C = C2; ldc = ldc2;
        n_real = n2; epi = epi2; bx = (bxi - nsplit) * 128;
    } else {
        bx = bxi * 128;
    }
    int by = blockIdx.y * 128;
    int wm = (wid >> 2) * 64, wn = (wid & 3) * 32;
    uint32_t smb = smem_to_u32(sm);

    float acc[4][4][4];
    #pragma unroll
    for (int i = 0; i < 4; ++i)
        #pragma unroll
        for (int j = 0; j < 4; ++j)
            #pragma unroll
            for (int r = 0; r < 4; ++r) acc[i][j][r] = 0.f;

    int T = K >> 5;

    auto load_stage = [&](int s) {
        uint32_t base = smb + (s % 3) * STG;
        int kb = s << 5;
        // A: 128 rows x 32 cols fp32 = 1024 16B-chunks
        #pragma unroll
        for (int i = 0; i < 4; ++i) {
            int pid = i * 256 + tid;
            int row = pid >> 3, ch = pid & 7;
            cp16(base + row * (ASTRIDE * 4) + ch * 16,
                 A + (size_t)(by + row) * lda + kb + ch * 4, 16);
        }
        // B: 32 k-rows x 128 cols fp32 = 1024 16B-chunks
        #pragma unroll
        for (int i = 0; i < 4; ++i) {
            int pid = i * 256 + tid;
            int k = pid >> 5, ch = pid & 31;
            int col = bx + ch * 4;
            bool v = col < n_real;
            const float* src = v ? (Bm + (size_t)(kb + k) * ldb + col) : Bm;
            cp16(base + ABYT + k * (BSTRIDE * 4) + ch * 16, src, v ? 16 : 0);
        }
    };

    load_stage(0); CP_COMMIT();
    if (T > 1) { load_stage(1); }
    CP_COMMIT();

    int arow = wm + (lane & 15);
    int acol4 = (lane >> 4) << 2;                 // 0 or 4 words
    int bk = lane & 3, bn = lane >> 2;

    for (int s = 0; s < T; ++s) {
        CP_WAIT1();
        __syncthreads();
        if (s + 2 < T) load_stage(s + 2);
        CP_COMMIT();

        uint32_t bA = smb + (s % 3) * STG;
        uint32_t abase = bA + (uint32_t)((arow * ASTRIDE + acol4) * 4);
        const uint32_t* Bs = (const uint32_t*)(sm + (s % 3) * STG + ABYT);

        #pragma unroll
        for (int q = 0; q < 4; ++q) {
            uint32_t a[4][4];
            #pragma unroll
            for (int mt = 0; mt < 4; ++mt)
                ldsm4(a[mt], abase + (uint32_t)(mt * 16 * ASTRIDE * 4 + q * 32));
            int rk = q * 8 + bk;
            uint32_t b0[4], b1[4];
            #pragma unroll
            for (int nt = 0; nt < 4; ++nt) {
                int col = wn + nt * 8 + bn;
                b0[nt] = Bs[rk * BSTRIDE + col];
                b1[nt] = Bs[(rk + 4) * BSTRIDE + col];
            }
            #pragma unroll
            for (int mt = 0; mt < 4; ++mt)
                #pragma unroll
                for (int nt = 0; nt < 4; ++nt)
                    mma_tf32(acc[mt][nt], a[mt], b0[nt], b1[nt]);
        }
    }

    // ---- epilogue ----
    #pragma unroll
    for (int mt = 0; mt < 4; ++mt) {
        #pragma unroll
        for (int nt = 0; nt < 4; ++nt) {
            int row0 = by + wm + mt * 16 + (lane >> 2);
            int col  = bx + wn + nt * 8 + (lane & 3) * 2;
            if (col < n_real) {
                float* a = acc[mt][nt];
                float2 v0 = make_float2(a[0], a[1]);
                float2 v1 = make_float2(a[2], a[3]);
                if (epi == 1) {
                    float2 e0 = *(const float2*)(extra + (size_t)row0 * lde + col);
                    float2 e1 = *(const float2*)(extra + (size_t)(row0 + 8) * lde + col);
                    v0.x += e0.x; v0.y += e0.y;
                    v1.x += e1.x; v1.y += e1.y;
                } else if (epi == 2) {
                    float b0 = extra[col], b1 = extra[col + 1];
                    v0.x = softplus_f(v0.x + b0);
                    v0.y = softplus_f(v0.y + b1);
                    v1.x = softplus_f(v1.x + b0);
                    v1.y = softplus_f(v1.y + b1);
                }
                *(float2*)(C + (size_t)row0 * ldc + col)       = v0;
                *(float2*)(C + (size_t)(row0 + 8) * ldc + col) = v1;
                if (epi == 3 && col < 64) {
                    g_dr_t[row0 * 64 + col]           = tf32r(v0.x);
                    g_dr_t[row0 * 64 + col + 1]       = tf32r(v0.y);
                    g_dr_t[(row0 + 8) * 64 + col]     = tf32r(v1.x);
                    g_dr_t[(row0 + 8) * 64 + col + 1] = tf32r(v1.y);
                }
            }
        }
    }
}

// ---------------- RMSNorm -> tf32-rounded u ----------------
__global__ void rmsnorm_kernel(const float* __restrict__ in,
                               const float* __restrict__ scale) {
    int l = blockIdx.x;
    int t = threadIdx.x;
    const float* row = in + (size_t)l * DM;
    float s = 0.f;
    for (int i = t; i < DM; i += 256) { float v = row[i]; s += v * v; }
    __shared__ float red[256];
    red[t] = s; __syncthreads();
    for (int o = 128; o > 0; o >>= 1) {
        if (t < o) red[t] += red[t + o];
        __syncthreads();
    }
    float inv = rsqrtf(red[0] * (1.f / DM) + 1e-6f);
    for (int i = t; i < DM; i += 256)
        g_u_t[(size_t)l * DM + i] = tf32r(row[i] * inv * scale[i]);
}

// ---------------- depthwise conv along d_inner + SiLU ----------------
__global__ void conv_silu_kernel(const float* __restrict__ cw,
                                 const float* __restrict__ cb) {
    int l = blockIdx.x;
    int t = threadIdx.x;
    __shared__ float xs[DI];
    const float4* src = (const float4*)(g_xres + (size_t)l * 2 * DI);
    float4* dst4 = (float4*)xs;
    for (int i = t; i < DI / 4; i += 256) dst4[i] = src[i];
    __syncthreads();
    float w0 = cw[l], w1 = cw[DI + l], w2 = cw[2 * DI + l], w3 = cw[3 * DI + l];
    float b = cb[l];
    for (int d = t; d < DI; d += 256) {
        float xm1 = (d > 0) ? xs[d - 1] : 0.f;
        float x0  = xs[d];
        float xp1 = (d < DI - 1) ? xs[d + 1] : 0.f;
        float xp2 = (d < DI - 2) ? xs[d + 2] : 0.f;
        float v = b + w0 * xm1 + w1 * x0 + w2 * xp1 + w3 * xp2;
        g_xconv[(size_t)l * DI + d] = v * (1.f / (1.f + __expf(-v)));
    }
}

// ---------------- selective scan, phase-split ----------------
__global__ void __launch_bounds__(256) scan_kernel(const float* __restrict__ A_log,
                                                   const float* __restrict__ Dp) {
    __shared__ float sdelta[16][16], sx[16][16], sB[16][16], sC[16][16], sres[16][16];
    __shared__ float sp[16 * 272 + 16];   // sp[i*272 + g*17 + n]
    int t = threadIdx.x;
    int g = t >> 4;
    int n = t & 15;
    int d0 = blockIdx.x * 16;
    int d  = d0 + g;

    float a = -expf(A_log[(size_t)d * DS + n]);
    float h = 0.f;
    int i2 = t >> 4;
    int g2 = t & 15;
    float Dd2 = Dp[d0 + g2];

    float pd = g_delta[(size_t)g * DI + d0 + n];
    float px = g_xconv[(size_t)g * DI + d0 + n];
    float pr = g_xres[(size_t)g * 2 * DI + DI + d0 + n];
    float pB = g_xdbl[(size_t)g * 96 + 64 + n];
    float pC = g_xdbl[(size_t)g * 96 + 80 + n];

    for (int l0 = 0; l0 < LSEQ; l0 += 16) {
        sdelta[g][n] = pd; sx[g][n] = px; sres[g][n] = pr; sB[g][n] = pB; sC[g][n] = pC;
        __syncthreads();
        if (l0 + 16 < LSEQ) {
            int l = l0 + 16 + g;
            pd = g_delta[(size_t)l * DI + d0 + n];
            px = g_xconv[(size_t)l * DI + d0 + n];
            pr = g_xres[(size_t)l * 2 * DI + DI + d0 + n];
            pB = g_xdbl[(size_t)l * 96 + 64 + n];
            pC = g_xdbl[(size_t)l * 96 + 80 + n];
        }
        #pragma unroll
        for (int i = 0; i < 16; ++i) {
            float dlt = sdelta[i][g];
            float dA  = __expf(dlt * a);
            h = fmaf(dA, h, dlt * sB[i][n] * sx[i][g]);
            sp[i * 272 + g * 17 + n] = h * sC[i][n];
        }
        __syncthreads();
        {
            const float* base = &sp[i2 * 272 + g2 * 17];
            float s0 = base[0] + base[1], s1 = base[2] + base[3];
            float s2 = base[4] + base[5], s3 = base[6] + base[7];
            float s4 = base[8] + base[9], s5 = base[10] + base[11];
            float s6 = base[12] + base[13], s7 = base[14] + base[15];
            float sum = ((s0 + s1) + (s2 + s3)) + ((s4 + s5) + (s6 + s7));
            float xv = sx[i2][g2];
            float r  = sres[i2][g2];
            float val = (sum + xv * Dd2) * (r / (1.f + __expf(-r)));
            g_y_t[(size_t)(l0 + i2) * DI + d0 + g2] = tf32r(val);
        }
        __syncthreads();
    }
}

// ---------------- launch ----------------
extern "C" void kernel_launch(void* const* d_in, const int* in_sizes, int n_in,
                              void* d_out, int out_size) {
    const float* inputs     = (const float*)d_in[0];
    const float* norm_scale = (const float*)d_in[1];
    const float* in_proj_w  = (const float*)d_in[2];
    const float* conv_w     = (const float*)d_in[3];
    const float* conv_b     = (const float*)d_in[4];
    const float* x_proj_w   = (const float*)d_in[5];
    const float* dt_proj_w  = (const float*)d_in[6];
    const float* dt_proj_b  = (const float*)d_in[7];
    const float* out_proj_w = (const float*)d_in[8];
    const float* A_log      = (const float*)d_in[9];
    const float* Dvec       = (const float*)d_in[10];
    float* out = (float*)d_out;

    void *p_xres, *p_xdbl, *p_delta, *p_u, *p_dr, *p_y;
    void *p_w1, *p_w2, *p_w3, *p_w4;
    cudaGetSymbolAddress(&p_xres, g_xres);
    cudaGetSymbolAddress(&p_xdbl, g_xdbl);
    cudaGetSymbolAddress(&p_delta, g_delta);
    cudaGetSymbolAddress(&p_u, g_u_t);
    cudaGetSymbolAddress(&p_dr, g_dr_t);
    cudaGetSymbolAddress(&p_y, g_y_t);
    cudaGetSymbolAddress(&p_w1, g_w1t);
    cudaGetSymbolAddress(&p_w2, g_w2t);
    cudaGetSymbolAddress(&p_w3, g_w3t);
    cudaGetSymbolAddress(&p_w4, g_w4t);

    const int SMEM = 3 * 35328;  // 105984
    cudaFuncSetAttribute(hgemm, cudaFuncAttributeMaxDynamicSharedMemorySize, SMEM);

    // 0) weight conversions (tf32 rounding)
    {
        const int NTOT = DM * 2 * DI / 4 + DM * 96 / 4 + 64 * DI / 4 + DI * DM / 4;
        convert_all<<<(NTOT + 255) / 256, 256>>>(
            in_proj_w,  (float*)p_w1,
            x_proj_w,   (float*)p_w2,
            dt_proj_w,  (float*)p_w3,
            out_proj_w, (float*)p_w4);
    }

    // 1) RMSNorm -> u (tf32-rounded)
    rmsnorm_kernel<<<LSEQ, 256>>>(inputs, norm_scale);

    // 2) fused G1+G2: blocks 0..31 -> in_proj (xres), block 32 -> x_proj (xdbl + dr_t)
    hgemm<<<dim3(33, 16), 256, SMEM>>>(
        (const float*)p_u, DM,
        (const float*)p_w1, 2 * DI,
        (float*)p_xres, 2 * DI, nullptr, 0,
        DM, 2 * DI, 0, 32,
        (const float*)p_w2, 96, (float*)p_xdbl, 96, 96, 3);

    // 3) conv + silu
    conv_silu_kernel<<<LSEQ, 256>>>(conv_w, conv_b);

    // 4) G3: dr @ dt_proj_w + bias, softplus -> delta
    hgemm<<<dim3(16, 16), 256, SMEM>>>(
        (const float*)p_dr, 64,
        (const float*)p_w3, DI,
        (float*)p_delta, DI, dt_proj_b, 0,
        64, DI, 2, 1 << 30,
        nullptr, 0, nullptr, 0, 0, 0);

    // 5) scan -> y (tf32-rounded)
    scan_kernel<<<DI / 16, 256>>>(A_log, Dvec);

    // 6) G4: y @ out_proj_w + inputs -> out
    hgemm<<<dim3(8, 16), 256, SMEM>>>(
        (const float*)p_y, DI,
        (const float*)p_w4, DM,
        out, DM, inputs, DM,
        DI, DM, 1, 1 << 30,
        nullptr, 0, nullptr, 0, 0, 0);
}

// round 11
// speedup vs baseline: 3.1828x; 1.0219x over previous
#include <cuda_runtime.h>
#include <cuda_bf16.h>
#include <cstdint>

#define LSEQ 2048
#define DM   1024
#define DI   2048
#define DS   16

// ---------------- scratch ----------------
__device__ float g_xres[LSEQ * 2 * DI];   // G1 out (x | res), fp32
__device__ float g_xconv[LSEQ * DI];      // conv+silu, fp32
__device__ float g_xdbl[LSEQ * 96];       // x_proj out, fp32 (B,C for scan)
__device__ float g_delta[LSEQ * DI];      // softplus delta, fp32
__device__ float g_u_t[LSEQ * DM];        // rmsnorm out, tf32-rounded
__device__ float g_dr_t[LSEQ * 64];       // delta_r, tf32-rounded
__device__ float g_y_t[LSEQ * DI];        // scan out, tf32-rounded
// tf32-rounded weights, TRANSPOSED to [N][K]
__device__ float g_w1t[2 * DI * DM];
__device__ float g_w2t[96 * DM];
__device__ float g_w3t[DI * 64];
__device__ float g_w4t[DM * DI];

__device__ __forceinline__ float softplus_f(float x) {
    return fmaxf(x, 0.f) + log1pf(__expf(-fabsf(x)));
}
__device__ __forceinline__ float tf32r(float x) {
    uint32_t r;
    asm("cvt.rna.tf32.f32 %0, %1;" : "=r"(r) : "f"(x));
    return __uint_as_float(r);
}
__device__ __forceinline__ uint32_t smem_to_u32(const void* p) {
    uint32_t a;
    asm("{ .reg .u64 t; cvta.to.shared.u64 t, %1; cvt.u32.u64 %0, t; }" : "=r"(a) : "l"(p));
    return a;
}
__device__ __forceinline__ void ldsm4(uint32_t* r, uint32_t addr) {
    asm volatile("ldmatrix.sync.aligned.m8n8.x4.shared.b16 {%0,%1,%2,%3}, [%4];"
                 : "=r"(r[0]), "=r"(r[1]), "=r"(r[2]), "=r"(r[3]) : "r"(addr));
}
__device__ __forceinline__ void mma_tf32(float* c, const uint32_t* a, uint32_t b0, uint32_t b1) {
    asm volatile("mma.sync.aligned.m16n8k8.row.col.f32.tf32.tf32.f32 "
                 "{%0,%1,%2,%3}, {%4,%5,%6,%7}, {%8,%9}, {%0,%1,%2,%3};"
                 : "+f"(c[0]), "+f"(c[1]), "+f"(c[2]), "+f"(c[3])
                 : "r"(a[0]), "r"(a[1]), "r"(a[2]), "r"(a[3]), "r"(b0), "r"(b1));
}
__device__ __forceinline__ void cp16(uint32_t dst, const void* src, int sz) {
    asm volatile("cp.async.cg.shared.global [%0], [%1], 16, %2;" :: "r"(dst), "l"(src), "r"(sz));
}
#define CP_COMMIT() asm volatile("cp.async.commit_group;" ::: "memory")
#define CP_WAIT1()  asm volatile("cp.async.wait_group 1;" ::: "memory")

// ---------------- tiled transpose + tf32 round: W[K][N] -> Wt[N][K] ----------------
__global__ void __launch_bounds__(256) conv_tr(const float* __restrict__ src,
                                               float* __restrict__ dst, int K, int N) {
    __shared__ float tile[32][33];
    int n0 = blockIdx.x * 32, k0 = blockIdx.y * 32;
    int tx = threadIdx.x & 31, ty = threadIdx.x >> 5;  // 32 x 8
    #pragma unroll
    for (int j = 0; j < 4; ++j)
        tile[ty + j * 8][tx] = tf32r(src[(size_t)(k0 + ty + j * 8) * N + n0 + tx]);
    __syncthreads();
    #pragma unroll
    for (int j = 0; j < 4; ++j)
        dst[(size_t)(n0 + ty + j * 8) * K + k0 + tx] = tile[tx][ty + j * 8];
}

// ---------------- tf32 HMMA GEMM, n-major B, all-ldsm fragments, occ 2 ----------------
// tile 128x128xBK32; 8 warps (2x4), warp 64x32.
// A smem [128 m][36 w], B smem [128 n][36 w] (both 144B rows).
// B gmem is PRE-TRANSPOSED [N][K] (k-contiguous), so both loaders are identical.
// epi: 0 plain, 1 +extra[r*lde+c], 2 softplus(acc+extra[c]), 3 plain + dr_t (c<64)
__global__ void __launch_bounds__(256, 2) hgemm(
    const float* __restrict__ A, int lda,
    const float* Bt, int ldbt,
    float* C, int ldc, const float* __restrict__ extra, int lde,
    int K, int n_real, int epi, int nsplit,
    const float* B2t, int ldb2t, float* C2, int ldc2, int n2, int epi2)
{
    extern __shared__ char sm[];
    constexpr int STRW = 36;                 // words per row
    constexpr int STRB = STRW * 4;           // 144 bytes
    constexpr int PL   = 128 * STRB;         // 18432 per matrix
    constexpr int STG  = 2 * PL;             // 36864 per stage

    int tid = threadIdx.x, wid = tid >> 5, lane = tid & 31;
    int bxi = blockIdx.x;
    int bx;
    if (bxi >= nsplit) {
        Bt = B2t; ldbt = ldb2t; C = C2; ldc = ldc2;
        n_real = n2; epi = epi2; bx = (bxi - nsplit) * 128;
    } else {
        bx = bxi * 128;
    }
    int by = blockIdx.y * 128;
    int wm = (wid >> 2) * 64, wn = (wid & 3) * 32;
    uint32_t smb = smem_to_u32(sm);

    float acc[4][4][4];
    #pragma unroll
    for (int i = 0; i < 4; ++i)
        #pragma unroll
        for (int j = 0; j < 4; ++j)
            #pragma unroll
            for (int r = 0; r < 4; ++r) acc[i][j][r] = 0.f;

    int T = K >> 5;

    auto load_stage = [&](int s) {
        uint32_t base = smb + (s % 3) * STG;
        int kb = s << 5;
        // A: 128 m-rows x 8 chunks
        #pragma unroll
        for (int i = 0; i < 4; ++i) {
            int pid = i * 256 + tid;
            int row = pid >> 3, ch = pid & 7;
            cp16(base + row * STRB + ch * 16,
                 A + (size_t)(by + row) * lda + kb + ch * 4, 16);
        }
        // B: 128 n-rows x 8 chunks (k-contiguous in Bt)
        #pragma unroll
        for (int i = 0; i < 4; ++i) {
            int pid = i * 256 + tid;
            int row = pid >> 3, ch = pid & 7;
            int n = bx + row;
            bool v = n < n_real;
            const float* src = v ? (Bt + (size_t)n * ldbt + kb + ch * 4) : Bt;
            cp16(base + PL + row * STRB + ch * 16, src, v ? 16 : 0);
        }
    };

    load_stage(0); CP_COMMIT();
    if (T > 1) { load_stage(1); }
    CP_COMMIT();

    // A ldsm lane addressing (row-major m16k8 tiles)
    int arow = wm + (lane & 15);
    int acol4 = (lane >> 4) << 2;             // 0 or 4 words
    // B ldsm lane addressing (n-major): grp = lane>>3
    int bgrp = lane >> 3, brr = lane & 7;
    int bcol = (bgrp >> 1) * 8 + brr;         // 0..15 within 16-col group
    uint32_t bko = (uint32_t)((bgrp & 1) * 16);

    for (int s = 0; s < T; ++s) {
        CP_WAIT1();
        __syncthreads();
        if (s + 2 < T) load_stage(s + 2);
        CP_COMMIT();

        uint32_t bA = smb + (s % 3) * STG;
        uint32_t abase = bA + (uint32_t)(arow * STRW + acol4) * 4;
        uint32_t bbase = bA + PL + (uint32_t)((wn + bcol) * STRB) + bko;

        #pragma unroll
        for (int q = 0; q < 4; ++q) {
            uint32_t a[4][4];
            #pragma unroll
            for (int mt = 0; mt < 4; ++mt)
                ldsm4(a[mt], abase + (uint32_t)(mt * 16 * STRB + q * 32));
            uint32_t bf0[4], bf1[4];
            ldsm4(bf0, bbase + (uint32_t)(q * 32));
            ldsm4(bf1, bbase + (uint32_t)(16 * STRB + q * 32));
            #pragma unroll
            for (int mt = 0; mt < 4; ++mt) {
                mma_tf32(acc[mt][0], a[mt], bf0[0], bf0[1]);
                mma_tf32(acc[mt][1], a[mt], bf0[2], bf0[3]);
                mma_tf32(acc[mt][2], a[mt], bf1[0], bf1[1]);
                mma_tf32(acc[mt][3], a[mt], bf1[2], bf1[3]);
            }
        }
    }

    // ---- epilogue ----
    #pragma unroll
    for (int mt = 0; mt < 4; ++mt) {
        #pragma unroll
        for (int nt = 0; nt < 4; ++nt) {
            int row0 = by + wm + mt * 16 + (lane >> 2);
            int col  = bx + wn + nt * 8 + (lane & 3) * 2;
            if (col < n_real) {
                float* a = acc[mt][nt];
                float2 v0 = make_float2(a[0], a[1]);
                float2 v1 = make_float2(a[2], a[3]);
                if (epi == 1) {
                    float2 e0 = *(const float2*)(extra + (size_t)row0 * lde + col);
                    float2 e1 = *(const float2*)(extra + (size_t)(row0 + 8) * lde + col);
                    v0.x += e0.x; v0.y += e0.y;
                    v1.x += e1.x; v1.y += e1.y;
                } else if (epi == 2) {
                    float b0 = extra[col], b1 = extra[col + 1];
                    v0.x = softplus_f(v0.x + b0);
                    v0.y = softplus_f(v0.y + b1);
                    v1.x = softplus_f(v1.x + b0);
                    v1.y = softplus_f(v1.y + b1);
                }
                *(float2*)(C + (size_t)row0 * ldc + col)       = v0;
                *(float2*)(C + (size_t)(row0 + 8) * ldc + col) = v1;
                if (epi == 3 && col < 64) {
                    g_dr_t[row0 * 64 + col]           = tf32r(v0.x);
                    g_dr_t[row0 * 64 + col + 1]       = tf32r(v0.y);
                    g_dr_t[(row0 + 8) * 64 + col]     = tf32r(v1.x);
                    g_dr_t[(row0 + 8) * 64 + col + 1] = tf32r(v1.y);
                }
            }
        }
    }
}

// ---------------- RMSNorm -> tf32-rounded u ----------------
__global__ void rmsnorm_kernel(const float* __restrict__ in,
                               const float* __restrict__ scale) {
    int l = blockIdx.x;
    int t = threadIdx.x;
    const float* row = in + (size_t)l * DM;
    float s = 0.f;
    for (int i = t; i < DM; i += 256) { float v = row[i]; s += v * v; }
    __shared__ float red[256];
    red[t] = s; __syncthreads();
    for (int o = 128; o > 0; o >>= 1) {
        if (t < o) red[t] += red[t + o];
        __syncthreads();
    }
    float inv = rsqrtf(red[0] * (1.f / DM) + 1e-6f);
    for (int i = t; i < DM; i += 256)
        g_u_t[(size_t)l * DM + i] = tf32r(row[i] * inv * scale[i]);
}

// ---------------- depthwise conv along d_inner + SiLU ----------------
__global__ void conv_silu_kernel(const float* __restrict__ cw,
                                 const float* __restrict__ cb) {
    int l = blockIdx.x;
    int t = threadIdx.x;
    __shared__ float xs[DI];
    const float4* src = (const float4*)(g_xres + (size_t)l * 2 * DI);
    float4* dst4 = (float4*)xs;
    for (int i = t; i < DI / 4; i += 256) dst4[i] = src[i];
    __syncthreads();
    float w0 = cw[l], w1 = cw[DI + l], w2 = cw[2 * DI + l], w3 = cw[3 * DI + l];
    float b = cb[l];
    for (int d = t; d < DI; d += 256) {
        float xm1 = (d > 0) ? xs[d - 1] : 0.f;
        float x0  = xs[d];
        float xp1 = (d < DI - 1) ? xs[d + 1] : 0.f;
        float xp2 = (d < DI - 2) ? xs[d + 2] : 0.f;
        float v = b + w0 * xm1 + w1 * x0 + w2 * xp1 + w3 * xp2;
        g_xconv[(size_t)l * DI + d] = v * (1.f / (1.f + __expf(-v)));
    }
}

// ---------------- selective scan, phase-split ----------------
__global__ void __launch_bounds__(256) scan_kernel(const float* __restrict__ A_log,
                                                   const float* __restrict__ Dp) {
    __shared__ float sdelta[16][16], sx[16][16], sB[16][16], sC[16][16], sres[16][16];
    __shared__ float sp[16 * 272 + 16];   // sp[i*272 + g*17 + n]
    int t = threadIdx.x;
    int g = t >> 4;
    int n = t & 15;
    int d0 = blockIdx.x * 16;
    int d  = d0 + g;

    float a = -expf(A_log[(size_t)d * DS + n]);
    float h = 0.f;
    int i2 = t >> 4;
    int g2 = t & 15;
    float Dd2 = Dp[d0 + g2];

    float pd = g_delta[(size_t)g * DI + d0 + n];
    float px = g_xconv[(size_t)g * DI + d0 + n];
    float pr = g_xres[(size_t)g * 2 * DI + DI + d0 + n];
    float pB = g_xdbl[(size_t)g * 96 + 64 + n];
    float pC = g_xdbl[(size_t)g * 96 + 80 + n];

    for (int l0 = 0; l0 < LSEQ; l0 += 16) {
        sdelta[g][n] = pd; sx[g][n] = px; sres[g][n] = pr; sB[g][n] = pB; sC[g][n] = pC;
        __syncthreads();
        if (l0 + 16 < LSEQ) {
            int l = l0 + 16 + g;
            pd = g_delta[(size_t)l * DI + d0 + n];
            px = g_xconv[(size_t)l * DI + d0 + n];
            pr = g_xres[(size_t)l * 2 * DI + DI + d0 + n];
            pB = g_xdbl[(size_t)l * 96 + 64 + n];
            pC = g_xdbl[(size_t)l * 96 + 80 + n];
        }
        #pragma unroll
        for (int i = 0; i < 16; ++i) {
            float dlt = sdelta[i][g];
            float dA  = __expf(dlt * a);
            h = fmaf(dA, h, dlt * sB[i][n] * sx[i][g]);
            sp[i * 272 + g * 17 + n] = h * sC[i][n];
        }
        __syncthreads();
        {
            const float* base = &sp[i2 * 272 + g2 * 17];
            float s0 = base[0] + base[1], s1 = base[2] + base[3];
            float s2 = base[4] + base[5], s3 = base[6] + base[7];
            float s4 = base[8] + base[9], s5 = base[10] + base[11];
            float s6 = base[12] + base[13], s7 = base[14] + base[15];
            float sum = ((s0 + s1) + (s2 + s3)) + ((s4 + s5) + (s6 + s7));
            float xv = sx[i2][g2];
            float r  = sres[i2][g2];
            float val = (sum + xv * Dd2) * (r / (1.f + __expf(-r)));
            g_y_t[(size_t)(l0 + i2) * DI + d0 + g2] = tf32r(val);
        }
        __syncthreads();
    }
}

// ---------------- launch ----------------
extern "C" void kernel_launch(void* const* d_in, const int* in_sizes, int n_in,
                              void* d_out, int out_size) {
    const float* inputs     = (const float*)d_in[0];
    const float* norm_scale = (const float*)d_in[1];
    const float* in_proj_w  = (const float*)d_in[2];
    const float* conv_w     = (const float*)d_in[3];
    const float* conv_b     = (const float*)d_in[4];
    const float* x_proj_w   = (const float*)d_in[5];
    const float* dt_proj_w  = (const float*)d_in[6];
    const float* dt_proj_b  = (const float*)d_in[7];
    const float* out_proj_w = (const float*)d_in[8];
    const float* A_log      = (const float*)d_in[9];
    const float* Dvec       = (const float*)d_in[10];
    float* out = (float*)d_out;

    void *p_xres, *p_xdbl, *p_delta, *p_u, *p_dr, *p_y;
    void *p_w1, *p_w2, *p_w3, *p_w4;
    cudaGetSymbolAddress(&p_xres, g_xres);
    cudaGetSymbolAddress(&p_xdbl, g_xdbl);
    cudaGetSymbolAddress(&p_delta, g_delta);
    cudaGetSymbolAddress(&p_u, g_u_t);
    cudaGetSymbolAddress(&p_dr, g_dr_t);
    cudaGetSymbolAddress(&p_y, g_y_t);
    cudaGetSymbolAddress(&p_w1, g_w1t);
    cudaGetSymbolAddress(&p_w2, g_w2t);
    cudaGetSymbolAddress(&p_w3, g_w3t);
    cudaGetSymbolAddress(&p_w4, g_w4t);

    const int SMEM = 3 * 36864;  // 110592
    cudaFuncSetAttribute(hgemm, cudaFuncAttributeMaxDynamicSharedMemorySize, SMEM);

    // 0) weight transpose + tf32 rounding: W[K][N] -> Wt[N][K]
    conv_tr<<<dim3(4096 / 32, 1024 / 32), 256>>>(in_proj_w,  (float*)p_w1, DM, 2 * DI);
    conv_tr<<<dim3(96 / 32,   1024 / 32), 256>>>(x_proj_w,   (float*)p_w2, DM, 96);
    conv_tr<<<dim3(2048 / 32, 64 / 32),   256>>>(dt_proj_w,  (float*)p_w3, 64, DI);
    conv_tr<<<dim3(1024 / 32, 2048 / 32), 256>>>(out_proj_w, (float*)p_w4, DI, DM);

    // 1) RMSNorm -> u (tf32-rounded)
    rmsnorm_kernel<<<LSEQ, 256>>>(inputs, norm_scale);

    // 2) fused G1+G2: blocks 0..31 -> in_proj (xres), block 32 -> x_proj (xdbl + dr_t)
    hgemm<<<dim3(33, 16), 256, SMEM>>>(
        (const float*)p_u, DM,
        (const float*)p_w1, DM,
        (float*)p_xres, 2 * DI, nullptr, 0,
        DM, 2 * DI, 0, 32,
        (const float*)p_w2, DM, (float*)p_xdbl, 96, 96, 3);

    // 3) conv + silu
    conv_silu_kernel<<<LSEQ, 256>>>(conv_w, conv_b);

    // 4) G3: dr @ dt_proj_w + bias, softplus -> delta
    hgemm<<<dim3(16, 16), 256, SMEM>>>(
        (const float*)p_dr, 64,
        (const float*)p_w3, 64,
        (float*)p_delta, DI, dt_proj_b, 0,
        64, DI, 2, 1 << 30,
        nullptr, 0, nullptr, 0, 0, 0);

    // 5) scan -> y (tf32-rounded)
    scan_kernel<<<DI / 16, 256>>>(A_log, Dvec);

    // 6) G4: y @ out_proj_w + inputs -> out
    hgemm<<<dim3(8, 16), 256, SMEM>>>(
        (const float*)p_y, DI,
        (const float*)p_w4, DI,
        out, DM, inputs, DM,
        DI, DM, 1, 1 << 30,
        nullptr, 0, nullptr, 0, 0, 0);
}